// round 3
// baseline (speedup 1.0000x reference)
#include <cuda_runtime.h>
#include <math.h>

// ---------------- problem constants ----------------
#define B_    4
#define C_    64
#define NPIX_ 16777216            // B*C*H*W
#define NT_   16384               // B * NPAT
#define TOK_  1024
#define SF_   2114
#define KSEL_ 1024
#define E_    128

// ---------------- device scratch ----------------
__device__ float2 g_cA[NPIX_];
__device__ float  g_ampV[NPIX_];
__device__ float  g_ampI[NPIX_];
__device__ float  g_phV [NPIX_];
__device__ float  g_phI [NPIX_];
__device__ float  g_faMap[NPIX_];
__device__ float  g_fpMap[NPIX_];
__device__ float  g_spatial[NPIX_];
__device__ float  g_r1[NPIX_];
__device__ float  g_scoreArr[NT_];
__device__ int    g_idxArr[B_ * KSEL_];
__device__ float  g_selV[(long)B_ * KSEL_ * TOK_];
__device__ float  g_selI[(long)B_ * KSEL_ * TOK_];
__device__ float  g_qb[B_ * KSEL_ * E_];
__device__ float  g_kb[B_ * KSEL_ * E_];
__device__ float  g_vb[B_ * KSEL_ * E_];
__device__ float  g_ob[B_ * KSEL_ * E_];
__device__ float  g_fs[(long)B_ * KSEL_ * TOK_];
__device__ float  g_gm[B_ * 2 * C_];
__device__ float  g_intentArr[B_ * 64];
__device__ float  g_t256r[256];
__device__ float  g_t256i[256];

// ---------------- twiddles ----------------
__global__ void twiddle_init_kernel() {
    int k = threadIdx.x;
    double a = -2.0 * 3.14159265358979323846 * (double)k / 256.0;
    g_t256r[k] = (float)cos(a);
    g_t256i[k] = (float)sin(a);
}

// ---------------- 16-point register FFT ----------------
__device__ __forceinline__ void fft16_reg(float* xr, float* xi, float dsign) {
    #define SW16_(a,b) { float t=xr[a]; xr[a]=xr[b]; xr[b]=t; t=xi[a]; xi[a]=xi[b]; xi[b]=t; }
    SW16_(1,8) SW16_(2,4) SW16_(3,12) SW16_(5,10) SW16_(7,14) SW16_(11,13)
    #undef SW16_
    const float C16[8] = {1.f, 0.9238795325112867f, 0.7071067811865476f, 0.3826834323650898f,
                          0.f, -0.3826834323650898f, -0.7071067811865476f, -0.9238795325112867f};
    const float S16[8] = {0.f, 0.3826834323650898f, 0.7071067811865476f, 0.9238795325112867f,
                          1.f, 0.9238795325112867f, 0.7071067811865476f, 0.3826834323650898f};
    #pragma unroll
    for (int s = 1; s <= 4; s++) {
        const int half = 1 << (s - 1);
        #pragma unroll
        for (int j = 0; j < 8; j++) {
            const int grp = j >> (s - 1);
            const int pos = j & (half - 1);
            const int i = (grp << s) + pos;
            const int l = i + half;
            const int ti = pos << (4 - s);
            float wr = C16[ti];
            float wi = -dsign * S16[ti];
            float vr = xr[l] * wr - xi[l] * wi;
            float vi = xr[l] * wi + xi[l] * wr;
            float ur = xr[i], ui = xi[i];
            xr[i] = ur + vr; xi[i] = ui + vi;
            xr[l] = ur - vr; xi[l] = ui - vi;
        }
    }
}

// ---------------- 256-pt FFT pass ----------------
#define FFT_SM 4352
__global__ void fft_pass2_kernel(const float2* __restrict__ cin,
                                 const float* __restrict__ rin,
                                 const float* __restrict__ fa,
                                 const float* __restrict__ fp,
                                 float2* __restrict__ cout,
                                 float* __restrict__ amp,
                                 float* __restrict__ ph,
                                 float* __restrict__ rout,
                                 int colmode, int dir, float scale) {
    __shared__ float sre[FFT_SM];
    __shared__ float sim[FFT_SM];
    int tid = threadIdx.x;
    int tx = tid & 15, ty = tid >> 4;
    int u = colmode ? ty : tx;
    int s = colmode ? tx : ty;
    int line = blockIdx.x * 16 + s;
    int plane = line >> 8, l = line & 255;
    long base; int stride;
    if (colmode) { base = (long)plane * 65536 + l; stride = 256; }
    else         { base = (long)plane * 65536 + (long)l * 256; stride = 1; }
    float dsign = (dir > 0) ? 1.f : -1.f;

    float xr[16], xi[16];
    #pragma unroll
    for (int n2 = 0; n2 < 16; n2++) {
        long a = base + (long)(u + 16 * n2) * stride;
        if (rin)      { xr[n2] = rin[a]; xi[n2] = 0.f; }
        else if (fa)  { float am = fa[a]; float sn, cs; sincosf(fp[a], &sn, &cs);
                        xr[n2] = am * cs; xi[n2] = am * sn; }
        else          { float2 c = cin[a]; xr[n2] = c.x; xi[n2] = c.y; }
    }
    fft16_reg(xr, xi, dsign);
    #pragma unroll
    for (int k2 = 0; k2 < 16; k2++) {
        int m = u * k2;
        float wr = g_t256r[m];
        float wi = dsign * g_t256i[m];
        float a = xr[k2], b = xi[k2];
        xr[k2] = a * wr - b * wi;
        xi[k2] = a * wi + b * wr;
    }
    #pragma unroll
    for (int k2 = 0; k2 < 16; k2++) {
        int idx = colmode ? ((k2 * 16 + u) * 17 + s) : (s * 272 + k2 * 17 + u);
        sre[idx] = xr[k2]; sim[idx] = xi[k2];
    }
    __syncthreads();
    #pragma unroll
    for (int n1 = 0; n1 < 16; n1++) {
        int idx = colmode ? ((u * 16 + n1) * 17 + s) : (s * 272 + u * 17 + n1);
        xr[n1] = sre[idx]; xi[n1] = sim[idx];
    }
    fft16_reg(xr, xi, dsign);
    #pragma unroll
    for (int k1 = 0; k1 < 16; k1++) {
        long a = base + (long)(16 * k1 + u) * stride;
        float rr = xr[k1] * scale, ii = xi[k1] * scale;
        if (cout)      cout[a] = make_float2(rr, ii);
        else if (amp)  { amp[a] = sqrtf(rr * rr + ii * ii); ph[a] = atan2f(ii, rr); }
        else           rout[a] = rr;
    }
}

// ---------------- router ----------------
__global__ void gap_kernel(const float* __restrict__ vis, const float* __restrict__ ir,
                           float* __restrict__ gm) {
    __shared__ float red[256];
    int b = blockIdx.x >> 7;
    int ch = blockIdx.x & 127;
    const float* p = (ch < 64) ? (vis + (long)(b * 64 + ch) * 65536)
                               : (ir  + (long)(b * 64 + ch - 64) * 65536);
    float s = 0.f;
    for (int i = threadIdx.x; i < 65536; i += 256) s += p[i];
    red[threadIdx.x] = s;
    __syncthreads();
    for (int st = 128; st > 0; st >>= 1) {
        if (threadIdx.x < st) red[threadIdx.x] += red[threadIdx.x + st];
        __syncthreads();
    }
    if (threadIdx.x == 0) gm[blockIdx.x] = red[0] * (1.0f / 65536.0f);
}

__global__ void router_kernel(const float* __restrict__ gm, const float* __restrict__ Wr,
                              const float* __restrict__ br, const float* __restrict__ bank,
                              float* __restrict__ intent) {
    __shared__ float pf[4][64];
    __shared__ float lg[4][4];
    __shared__ float w[4][4];
    int t = threadIdx.x;
    for (int b = 0; b < 4; b++) {
        float s = br[t];
        for (int c = 0; c < 128; c++) s += gm[b * 128 + c] * Wr[c * 64 + t];
        pf[b][t] = s;
    }
    __syncthreads();
    if (t < 16) {
        int b = t >> 2, j = t & 3;
        float s = 0.f;
        for (int p = 0; p < 64; p++) s += pf[b][p] * bank[j * 64 + p];
        lg[b][j] = s;
    }
    __syncthreads();
    if (t < 4) {
        int b = t;
        float m = fmaxf(fmaxf(lg[b][0], lg[b][1]), fmaxf(lg[b][2], lg[b][3]));
        float e0 = expf(lg[b][0] - m), e1 = expf(lg[b][1] - m);
        float e2 = expf(lg[b][2] - m), e3 = expf(lg[b][3] - m);
        float s = e0 + e1 + e2 + e3;
        w[b][0] = e0 / s; w[b][1] = e1 / s; w[b][2] = e2 / s; w[b][3] = e3 / s;
    }
    __syncthreads();
    for (int b = 0; b < 4; b++) {
        float s = 0.f;
        for (int j = 0; j < 4; j++) s += w[b][j] * bank[j * 64 + t];
        intent[b * 64 + t] = s;
    }
}

// ---------------- fused score net: 128x128 tile, 8x8 micro ----------------
__global__ void __launch_bounds__(256) score_fused_kernel(
        const float* __restrict__ mapV, const float* __restrict__ mapI,
        const float* __restrict__ intent,
        const float* __restrict__ W1, const float* __restrict__ b1,
        const float* __restrict__ W2, const float* __restrict__ b2,
        float* __restrict__ score) {
    const int BK = 16;
    __shared__ float As[BK][132];
    __shared__ float Bs[BK][132];
    __shared__ float red[128 * 16];
    int tid = threadIdx.x;
    int row0 = blockIdx.x * 128;
    int ty = tid >> 4, tx = tid & 15;

    float acc[8][8];
    #pragma unroll
    for (int i = 0; i < 8; i++)
        #pragma unroll
        for (int j = 0; j < 8; j++) acc[i][j] = 0.f;

    for (int k0 = 0; k0 < SF_; k0 += BK) {
        // A tile 128x16, generated on the fly
        #pragma unroll
        for (int lq = 0; lq < 8; lq++) {
            int e = tid + lq * 256;
            int r = e >> 4, c = e & 15;
            int col = k0 + c;
            int tok = row0 + r;
            int b = tok >> 12, n = tok & 4095;
            float v = 0.f;
            if (col < 2048) {
                int t = col & 1023;
                int ch = t >> 4, py = (t >> 2) & 3, px = t & 3;
                int hy = n >> 6, wx = n & 63;
                long m = (((long)(b * 64 + ch) * 256) + hy * 4 + py) * 256 + wx * 4 + px;
                v = (col < 1024) ? mapV[m] : mapI[m];
            } else if (col < SF_) {
                if (col == 2048)      v = (float)(n >> 6) * (1.0f / 63.0f);
                else if (col == 2049) v = (float)(n & 63) * (1.0f / 63.0f);
                else                  v = intent[b * 64 + (col - 2050)];
            }
            As[c][r] = v;
        }
        // B tile 16x128
        #pragma unroll
        for (int lq = 0; lq < 8; lq++) {
            int e = tid + lq * 256;
            int r = e >> 7, c = e & 127;
            Bs[r][c] = (k0 + r < SF_) ? W1[(long)(k0 + r) * 128 + c] : 0.f;
        }
        __syncthreads();
        #pragma unroll
        for (int kk = 0; kk < BK; kk++) {
            float a[8], bb[8];
            float4 a0 = *(const float4*)&As[kk][ty * 8];
            float4 a1 = *(const float4*)&As[kk][ty * 8 + 4];
            a[0]=a0.x; a[1]=a0.y; a[2]=a0.z; a[3]=a0.w;
            a[4]=a1.x; a[5]=a1.y; a[6]=a1.z; a[7]=a1.w;
            float4 b0 = *(const float4*)&Bs[kk][tx * 4];        // cols tx*4..+3
            float4 b1v = *(const float4*)&Bs[kk][64 + tx * 4];  // cols 64+tx*4..+3
            bb[0]=b0.x; bb[1]=b0.y; bb[2]=b0.z; bb[3]=b0.w;
            bb[4]=b1v.x; bb[5]=b1v.y; bb[6]=b1v.z; bb[7]=b1v.w;
            #pragma unroll
            for (int i = 0; i < 8; i++)
                #pragma unroll
                for (int j = 0; j < 8; j++) acc[i][j] += a[i] * bb[j];
        }
        __syncthreads();
    }

    // epilogue: relu(acc + b1) dot W2 -> per-row partials -> reduce
    float w2[8], bs[8];
    #pragma unroll
    for (int j = 0; j < 4; j++) { w2[j] = W2[tx * 4 + j];      bs[j] = b1[tx * 4 + j]; }
    #pragma unroll
    for (int j = 0; j < 4; j++) { w2[4 + j] = W2[64 + tx * 4 + j]; bs[4 + j] = b1[64 + tx * 4 + j]; }
    #pragma unroll
    for (int i = 0; i < 8; i++) {
        float p = 0.f;
        #pragma unroll
        for (int j = 0; j < 8; j++) {
            float h = fmaxf(acc[i][j] + bs[j], 0.f);
            p += h * w2[j];
        }
        red[(ty * 8 + i) * 16 + tx] = p;
    }
    __syncthreads();
    if (tid < 128) {
        float s = 0.f;
        #pragma unroll
        for (int q = 0; q < 16; q++) s += red[tid * 16 + q];
        score[row0 + tid] = s + b2[0];
    }
}

// ---------------- generic fp32 GEMM ----------------
__global__ void gemm_kernel(const float* __restrict__ A, const float* __restrict__ Bm,
                            float* __restrict__ C, const float* __restrict__ bias,
                            const float* __restrict__ residual,
                            int M, int N, int K, int act) {
    const int BM = 64, BN = 64, BK = 16;
    __shared__ float As[BK][BM];
    __shared__ float Bs[BK][BN + 1];
    int tid = threadIdx.x;
    int row0 = blockIdx.y * BM, col0 = blockIdx.x * BN;
    int ty = tid >> 4, tx = tid & 15;
    float acc[4][4];
    #pragma unroll
    for (int i = 0; i < 4; i++)
        #pragma unroll
        for (int j = 0; j < 4; j++) acc[i][j] = 0.f;

    for (int k0 = 0; k0 < K; k0 += BK) {
        #pragma unroll
        for (int l = 0; l < 4; l++) {
            int e = tid + l * 256;
            int r = e >> 4, c = e & 15;
            int gr = row0 + r, gc = k0 + c;
            As[c][r] = (gr < M && gc < K) ? A[(long)gr * K + gc] : 0.f;
        }
        #pragma unroll
        for (int l = 0; l < 4; l++) {
            int e = tid + l * 256;
            int r = e >> 6, c = e & 63;
            int gr = k0 + r, gc = col0 + c;
            Bs[r][c] = (gr < K && gc < N) ? Bm[(long)gr * N + gc] : 0.f;
        }
        __syncthreads();
        #pragma unroll
        for (int kk = 0; kk < BK; kk++) {
            float a[4], b[4];
            #pragma unroll
            for (int i = 0; i < 4; i++) a[i] = As[kk][ty * 4 + i];
            #pragma unroll
            for (int j = 0; j < 4; j++) b[j] = Bs[kk][tx * 4 + j];
            #pragma unroll
            for (int i = 0; i < 4; i++)
                #pragma unroll
                for (int j = 0; j < 4; j++) acc[i][j] += a[i] * b[j];
        }
        __syncthreads();
    }
    #pragma unroll
    for (int i = 0; i < 4; i++) {
        int r = row0 + ty * 4 + i;
        if (r >= M) continue;
        #pragma unroll
        for (int j = 0; j < 4; j++) {
            int c = col0 + tx * 4 + j;
            if (c >= N) continue;
            float v = acc[i][j];
            if (bias) v += bias[c];
            if (residual) v += residual[(long)r * N + c];
            if (act) v = fmaxf(v, 0.f);
            C[(long)r * N + c] = v;
        }
    }
}

// ---------------- top-k via bitonic sort ----------------
__global__ void __launch_bounds__(1024) topk_kernel(const float* __restrict__ score,
                                                    int* __restrict__ idxo) {
    __shared__ float key[4096];
    __shared__ int val[4096];
    int b = blockIdx.x;
    int t = threadIdx.x;
    for (int i = t; i < 4096; i += 1024) { key[i] = score[b * 4096 + i]; val[i] = i; }
    __syncthreads();
    for (int k = 2; k <= 4096; k <<= 1) {
        for (int j = k >> 1; j > 0; j >>= 1) {
            for (int i = t; i < 4096; i += 1024) {
                int ixj = i ^ j;
                if (ixj > i) {
                    bool desc = ((i & k) == 0);
                    float a = key[i], c = key[ixj];
                    bool sw = desc ? (a < c) : (a > c);
                    if (sw) {
                        key[i] = c; key[ixj] = a;
                        int tv = val[i]; val[i] = val[ixj]; val[ixj] = tv;
                    }
                }
            }
            __syncthreads();
        }
    }
    if (t < 1024) idxo[b * 1024 + t] = val[t];
}

// ---------------- gather / scatter ----------------
__device__ __forceinline__ long patch_pixel(int b, int n, int t) {
    int hy = n >> 6, wx = n & 63;
    int c = t >> 4, py = (t >> 2) & 3, px = t & 3;
    return (((long)(b * 64 + c) * 256) + hy * 4 + py) * 256 + wx * 4 + px;
}

__global__ void gather_kernel(const float* __restrict__ mapV, const float* __restrict__ mapI,
                              const int* __restrict__ idx,
                              float* __restrict__ selV, float* __restrict__ selI) {
    long gid = (long)blockIdx.x * 256 + threadIdx.x;
    int bi = (int)(gid >> 10);
    int t = (int)(gid & 1023);
    int b = bi >> 10;
    int n = idx[bi];
    long m = patch_pixel(b, n, t);
    selV[gid] = mapV[m];
    selI[gid] = mapI[m];
}

__global__ void scatter_kernel(const float* __restrict__ fs, const int* __restrict__ idx,
                               float* __restrict__ outMap) {
    long gid = (long)blockIdx.x * 256 + threadIdx.x;
    int bi = (int)(gid >> 10);
    int t = (int)(gid & 1023);
    int b = bi >> 10;
    int n = idx[bi];
    long m = patch_pixel(b, n, t);
    outMap[m] = fs[gid];
}

// ---------------- flash attention: Q tile 64, online softmax ----------------
__global__ void __launch_bounds__(256) flash_attn_kernel(
        const float* __restrict__ Q, const float* __restrict__ K,
        const float* __restrict__ V, float* __restrict__ O) {
    __shared__ float Qs[64][33];
    __shared__ float Ks[64][33];
    __shared__ float Vs[64][33];
    __shared__ float Ss[64][65];
    __shared__ float mrow[64], lrow[64], scf[64];
    __shared__ float pmax[4][64], psum[4][64];
    int tid = threadIdx.x;
    int z = blockIdx.y;
    int b = z >> 2, h = z & 3;
    int i0 = blockIdx.x * 64;
    const float scale = 0.17677669529663687f;   // 1/sqrt(32)

    #pragma unroll
    for (int l = 0; l < 8; l++) {
        int e = tid + l * 256;
        int r = e >> 5, c = e & 31;
        Qs[r][c] = Q[(long)(b * 1024 + i0 + r) * 128 + h * 32 + c];
    }
    if (tid < 64) { mrow[tid] = -3.4e38f; lrow[tid] = 0.f; }
    int ty = tid >> 4, tx = tid & 15;
    int row = tid & 63, qd = tid >> 6;
    float oacc[4][2];
    #pragma unroll
    for (int i = 0; i < 4; i++) { oacc[i][0] = 0.f; oacc[i][1] = 0.f; }
    __syncthreads();

    for (int j0 = 0; j0 < 1024; j0 += 64) {
        #pragma unroll
        for (int l = 0; l < 8; l++) {
            int e = tid + l * 256;
            int r = e >> 5, c = e & 31;
            Ks[r][c] = K[(long)(b * 1024 + j0 + r) * 128 + h * 32 + c];
            Vs[r][c] = V[(long)(b * 1024 + j0 + r) * 128 + h * 32 + c];
        }
        __syncthreads();
        // S tile: 4x4 per thread
        float s[4][4];
        #pragma unroll
        for (int i = 0; i < 4; i++)
            #pragma unroll
            for (int j = 0; j < 4; j++) s[i][j] = 0.f;
        #pragma unroll
        for (int d = 0; d < 32; d++) {
            float a[4], bb[4];
            #pragma unroll
            for (int i = 0; i < 4; i++) a[i] = Qs[ty * 4 + i][d];
            #pragma unroll
            for (int j = 0; j < 4; j++) bb[j] = Ks[tx * 4 + j][d];
            #pragma unroll
            for (int i = 0; i < 4; i++)
                #pragma unroll
                for (int j = 0; j < 4; j++) s[i][j] += a[i] * bb[j];
        }
        #pragma unroll
        for (int i = 0; i < 4; i++)
            #pragma unroll
            for (int j = 0; j < 4; j++) Ss[ty * 4 + i][tx * 4 + j] = s[i][j] * scale;
        __syncthreads();
        // partial row max (each thread: one row, 16 cols)
        float pm = -3.4e38f;
        #pragma unroll
        for (int c = 0; c < 16; c++) pm = fmaxf(pm, Ss[row][qd * 16 + c]);
        pmax[qd][row] = pm;
        __syncthreads();
        if (tid < 64) {
            float mn = fmaxf(fmaxf(pmax[0][tid], pmax[1][tid]),
                             fmaxf(pmax[2][tid], pmax[3][tid]));
            mn = fmaxf(mn, mrow[tid]);
            scf[tid] = __expf(mrow[tid] - mn);
            mrow[tid] = mn;
        }
        __syncthreads();
        float mn = mrow[row];
        float ps = 0.f;
        #pragma unroll
        for (int c = 0; c < 16; c++) {
            float e = __expf(Ss[row][qd * 16 + c] - mn);
            Ss[row][qd * 16 + c] = e;
            ps += e;
        }
        psum[qd][row] = ps;
        __syncthreads();
        if (tid < 64)
            lrow[tid] = lrow[tid] * scf[tid] + psum[0][tid] + psum[1][tid] + psum[2][tid] + psum[3][tid];
        // rescale running O and accumulate P@V
        #pragma unroll
        for (int i = 0; i < 4; i++) {
            float sc = scf[ty * 4 + i];
            oacc[i][0] *= sc; oacc[i][1] *= sc;
        }
        #pragma unroll
        for (int kk = 0; kk < 64; kk++) {
            float v0 = Vs[kk][tx * 2], v1 = Vs[kk][tx * 2 + 1];
            #pragma unroll
            for (int i = 0; i < 4; i++) {
                float p = Ss[ty * 4 + i][kk];
                oacc[i][0] += p * v0;
                oacc[i][1] += p * v1;
            }
        }
        __syncthreads();
    }
    #pragma unroll
    for (int i = 0; i < 4; i++) {
        float inv = 1.0f / lrow[ty * 4 + i];
        long obase = (long)(b * 1024 + i0 + ty * 4 + i) * 128 + h * 32 + tx * 2;
        O[obase]     = oacc[i][0] * inv;
        O[obase + 1] = oacc[i][1] * inv;
    }
}

// ---------------- elementwise avg ----------------
__global__ void avg_kernel(const float* __restrict__ a, const float* __restrict__ b,
                           float* __restrict__ o) {
    int i = blockIdx.x * 256 + threadIdx.x;
    o[i] = 0.5f * (a[i] + b[i]);
}

// ---------------- 3x3 SAME conv: 32x32 pixel tile, 16 co / block, 4 px / thread ----------------
__global__ void __launch_bounds__(256) conv3_kernel(
        const float* __restrict__ in, const float* __restrict__ wgt,
        const float* __restrict__ bias, float* __restrict__ out,
        const float* __restrict__ resA, const float* __restrict__ resB,
        int relu) {
    __shared__ float sIn[34][36];
    __shared__ float sW[16][9];
    int bz = blockIdx.z;
    int batch = bz >> 2, cg = bz & 3;
    int x0 = blockIdx.x * 32, y0 = blockIdx.y * 32;
    int tid = threadIdx.x;
    int tx = tid & 15, ty = tid >> 4;
    float acc[16][4];
    #pragma unroll
    for (int co = 0; co < 16; co++)
        #pragma unroll
        for (int q = 0; q < 4; q++) acc[co][q] = 0.f;

    for (int ci = 0; ci < 64; ci++) {
        const float* ip = in + (long)(batch * 64 + ci) * 65536;
        for (int e = tid; e < 1156; e += 256) {
            int ry = e / 34, rx = e % 34;
            int gy = y0 + ry - 1, gx = x0 + rx - 1;
            sIn[ry][rx] = (gy >= 0 && gy < 256 && gx >= 0 && gx < 256) ? ip[gy * 256 + gx] : 0.f;
        }
        if (tid < 144) {
            int co = tid / 9, k = tid % 9;
            sW[co][k] = wgt[((long)(cg * 16 + co) * 64 + ci) * 9 + k];
        }
        __syncthreads();
        float vv[4][9];
        #pragma unroll
        for (int a = 0; a < 2; a++)
            #pragma unroll
            for (int bq = 0; bq < 2; bq++)
                #pragma unroll
                for (int ky = 0; ky < 3; ky++)
                    #pragma unroll
                    for (int kx = 0; kx < 3; kx++)
                        vv[a * 2 + bq][ky * 3 + kx] = sIn[ty + a * 16 + ky][tx + bq * 16 + kx];
        #pragma unroll
        for (int co = 0; co < 16; co++) {
            #pragma unroll
            for (int k = 0; k < 9; k++) {
                float w = sW[co][k];
                acc[co][0] += vv[0][k] * w;
                acc[co][1] += vv[1][k] * w;
                acc[co][2] += vv[2][k] * w;
                acc[co][3] += vv[3][k] * w;
            }
        }
        __syncthreads();
    }
    #pragma unroll
    for (int co = 0; co < 16; co++) {
        int gco = cg * 16 + co;
        float bsv = bias[gco];
        #pragma unroll
        for (int a = 0; a < 2; a++) {
            #pragma unroll
            for (int bq = 0; bq < 2; bq++) {
                int y = y0 + ty + a * 16, x = x0 + tx + bq * 16;
                long oidx = ((long)(batch * 64 + gco) * 256 + y) * 256 + x;
                float v = acc[co][a * 2 + bq] + bsv;
                if (relu) v = fmaxf(v, 0.f);
                if (resA) v += 0.5f * (resA[oidx] + resB[oidx]);
                out[oidx] = v;
            }
        }
    }
}

// ---------------- host-side branch driver ----------------
static void run_branch(const float* mapV, const float* mapI,
                       const float* W1, const float* b1,
                       const float* W2, const float* b2,
                       const float* Wq, const float* Wk, const float* Wv, const float* Wo,
                       const float* intent,
                       float* score, int* idxp,
                       float* selV, float* selI,
                       float* q, float* k, float* v, float* o,
                       float* fs, float* outMap) {
    score_fused_kernel<<<128, 256>>>(mapV, mapI, intent, W1, b1, W2, b2, score);
    topk_kernel<<<4, 1024>>>(score, idxp);
    gather_kernel<<<16384, 256>>>(mapV, mapI, idxp, selV, selI);
    gemm_kernel<<<dim3(2, 64), 256>>>(selV, Wq, q, nullptr, nullptr, 4096, 128, 1024, 0);
    gemm_kernel<<<dim3(2, 64), 256>>>(selI, Wk, k, nullptr, nullptr, 4096, 128, 1024, 0);
    gemm_kernel<<<dim3(2, 64), 256>>>(selI, Wv, v, nullptr, nullptr, 4096, 128, 1024, 0);
    flash_attn_kernel<<<dim3(16, 16), 256>>>(q, k, v, o);
    gemm_kernel<<<dim3(16, 64), 256>>>(o, Wo, fs, nullptr, selV, 4096, 1024, 128, 0);
    avg_kernel<<<65536, 256>>>(mapV, mapI, outMap);
    scatter_kernel<<<16384, 256>>>(fs, idxp, outMap);
}

extern "C" void kernel_launch(void* const* d_in, const int* in_sizes, int n_in,
                              void* d_out, int out_size) {
    const float* vis  = (const float*)d_in[0];
    const float* ir   = (const float*)d_in[1];
    const float* bank = (const float*)d_in[2];
    const float* Wr   = (const float*)d_in[3];
    const float* br   = (const float*)d_in[4];
    const float* aW1  = (const float*)d_in[5];
    const float* ab1  = (const float*)d_in[6];
    const float* aW2  = (const float*)d_in[7];
    const float* ab2  = (const float*)d_in[8];
    const float* aWq  = (const float*)d_in[9];
    const float* aWk  = (const float*)d_in[10];
    const float* aWv  = (const float*)d_in[11];
    const float* aWo  = (const float*)d_in[12];
    const float* pW1  = (const float*)d_in[13];
    const float* pb1  = (const float*)d_in[14];
    const float* pW2  = (const float*)d_in[15];
    const float* pb2  = (const float*)d_in[16];
    const float* pWq  = (const float*)d_in[17];
    const float* pWk  = (const float*)d_in[18];
    const float* pWv  = (const float*)d_in[19];
    const float* pWo  = (const float*)d_in[20];
    const float* c1w  = (const float*)d_in[21];
    const float* c1b  = (const float*)d_in[22];
    const float* c2w  = (const float*)d_in[23];
    const float* c2b  = (const float*)d_in[24];
    float* out = (float*)d_out;

    float2* cA;
    float *ampV, *ampI, *phV, *phI, *faMap, *fpMap, *spatial, *r1;
    float *score, *selV, *selI, *q, *k, *v, *o, *fs, *gm, *intent;
    int* idxp;
    cudaGetSymbolAddress((void**)&cA, g_cA);
    cudaGetSymbolAddress((void**)&ampV, g_ampV);
    cudaGetSymbolAddress((void**)&ampI, g_ampI);
    cudaGetSymbolAddress((void**)&phV, g_phV);
    cudaGetSymbolAddress((void**)&phI, g_phI);
    cudaGetSymbolAddress((void**)&faMap, g_faMap);
    cudaGetSymbolAddress((void**)&fpMap, g_fpMap);
    cudaGetSymbolAddress((void**)&spatial, g_spatial);
    cudaGetSymbolAddress((void**)&r1, g_r1);
    cudaGetSymbolAddress((void**)&score, g_scoreArr);
    cudaGetSymbolAddress((void**)&idxp, g_idxArr);
    cudaGetSymbolAddress((void**)&selV, g_selV);
    cudaGetSymbolAddress((void**)&selI, g_selI);
    cudaGetSymbolAddress((void**)&q, g_qb);
    cudaGetSymbolAddress((void**)&k, g_kb);
    cudaGetSymbolAddress((void**)&v, g_vb);
    cudaGetSymbolAddress((void**)&o, g_ob);
    cudaGetSymbolAddress((void**)&fs, g_fs);
    cudaGetSymbolAddress((void**)&gm, g_gm);
    cudaGetSymbolAddress((void**)&intent, g_intentArr);

    twiddle_init_kernel<<<1, 256>>>();
    gap_kernel<<<512, 256>>>(vis, ir, gm);
    router_kernel<<<1, 64>>>(gm, Wr, br, bank, intent);

    const int FB = 4096;
    fft_pass2_kernel<<<FB, 256>>>(nullptr, vis, nullptr, nullptr, cA, nullptr, nullptr, nullptr, 0, +1, 1.f);
    fft_pass2_kernel<<<FB, 256>>>(cA, nullptr, nullptr, nullptr, nullptr, ampV, phV, nullptr, 1, +1, 1.f);
    fft_pass2_kernel<<<FB, 256>>>(nullptr, ir, nullptr, nullptr, cA, nullptr, nullptr, nullptr, 0, +1, 1.f);
    fft_pass2_kernel<<<FB, 256>>>(cA, nullptr, nullptr, nullptr, nullptr, ampI, phI, nullptr, 1, +1, 1.f);

    run_branch(ampV, ampI, aW1, ab1, aW2, ab2, aWq, aWk, aWv, aWo, intent,
               score, idxp, selV, selI, q, k, v, o, fs, faMap);
    run_branch(phV, phI, pW1, pb1, pW2, pb2, pWq, pWk, pWv, pWo, intent,
               score, idxp, selV, selI, q, k, v, o, fs, fpMap);

    fft_pass2_kernel<<<FB, 256>>>(nullptr, nullptr, faMap, fpMap, cA, nullptr, nullptr, nullptr, 0, -1, 1.f);
    fft_pass2_kernel<<<FB, 256>>>(cA, nullptr, nullptr, nullptr, nullptr, nullptr, nullptr, spatial, 1, -1, 1.0f / 65536.0f);

    conv3_kernel<<<dim3(8, 8, 16), 256>>>(spatial, c1w, c1b, r1, nullptr, nullptr, 1);
    conv3_kernel<<<dim3(8, 8, 16), 256>>>(r1, c2w, c2b, out, vis, ir, 0);

    (void)in_sizes; (void)n_in; (void)out_size;
}

// round 4
// speedup vs baseline: 1.0230x; 1.0230x over previous
#include <cuda_runtime.h>
#include <math.h>

// ---------------- problem constants ----------------
#define B_    4
#define C_    64
#define NPIX_ 16777216            // B*C*H*W
#define NT_   16384               // B * NPAT
#define TOK_  1024
#define SF_   2114
#define KSEL_ 1024
#define E_    128

// ---------------- device scratch ----------------
__device__ float2 g_cA[NPIX_];
__device__ float  g_ampV[NPIX_];
__device__ float  g_ampI[NPIX_];
__device__ float  g_phV [NPIX_];
__device__ float  g_phI [NPIX_];
__device__ float  g_faMap[NPIX_];
__device__ float  g_fpMap[NPIX_];
__device__ float  g_spatial[NPIX_];
__device__ float  g_r1[NPIX_];
__device__ float  g_scoreArr[NT_];
__device__ int    g_idxArr[B_ * KSEL_];
__device__ float  g_selV[(long)B_ * KSEL_ * TOK_];
__device__ float  g_selI[(long)B_ * KSEL_ * TOK_];
__device__ float  g_qb[B_ * KSEL_ * E_];
__device__ float  g_kb[B_ * KSEL_ * E_];
__device__ float  g_vb[B_ * KSEL_ * E_];
__device__ float  g_ob[B_ * KSEL_ * E_];
__device__ float  g_att[(long)B_ * 4 * KSEL_ * KSEL_];
__device__ float  g_fs[(long)B_ * KSEL_ * TOK_];
__device__ float  g_gm[B_ * 2 * C_];
__device__ float  g_intentArr[B_ * 64];
__device__ float  g_t256r[256];
__device__ float  g_t256i[256];

// ---------------- packed f32x2 helpers (sm_103a FFMA2) ----------------
__device__ __forceinline__ unsigned long long pk2(float lo, float hi) {
    unsigned long long r;
    asm("mov.b64 %0, {%1, %2};" : "=l"(r) : "f"(lo), "f"(hi));
    return r;
}
__device__ __forceinline__ void upk2(unsigned long long v, float& lo, float& hi) {
    asm("mov.b64 {%0, %1}, %2;" : "=f"(lo), "=f"(hi) : "l"(v));
}
#define FMA2_(d, a, b) asm("fma.rn.f32x2 %0, %1, %2, %0;" : "+l"(d) : "l"(a), "l"(b))

// ---------------- twiddles ----------------
__global__ void twiddle_init_kernel() {
    int k = threadIdx.x;
    double a = -2.0 * 3.14159265358979323846 * (double)k / 256.0;
    g_t256r[k] = (float)cos(a);
    g_t256i[k] = (float)sin(a);
}

// ---------------- 16-point register FFT ----------------
__device__ __forceinline__ void fft16_reg(float* xr, float* xi, float dsign) {
    #define SW16_(a,b) { float t=xr[a]; xr[a]=xr[b]; xr[b]=t; t=xi[a]; xi[a]=xi[b]; xi[b]=t; }
    SW16_(1,8) SW16_(2,4) SW16_(3,12) SW16_(5,10) SW16_(7,14) SW16_(11,13)
    #undef SW16_
    const float C16[8] = {1.f, 0.9238795325112867f, 0.7071067811865476f, 0.3826834323650898f,
                          0.f, -0.3826834323650898f, -0.7071067811865476f, -0.9238795325112867f};
    const float S16[8] = {0.f, 0.3826834323650898f, 0.7071067811865476f, 0.9238795325112867f,
                          1.f, 0.9238795325112867f, 0.7071067811865476f, 0.3826834323650898f};
    #pragma unroll
    for (int s = 1; s <= 4; s++) {
        const int half = 1 << (s - 1);
        #pragma unroll
        for (int j = 0; j < 8; j++) {
            const int grp = j >> (s - 1);
            const int pos = j & (half - 1);
            const int i = (grp << s) + pos;
            const int l = i + half;
            const int ti = pos << (4 - s);
            float wr = C16[ti];
            float wi = -dsign * S16[ti];
            float vr = xr[l] * wr - xi[l] * wi;
            float vi = xr[l] * wi + xi[l] * wr;
            float ur = xr[i], ui = xi[i];
            xr[i] = ur + vr; xi[i] = ui + vi;
            xr[l] = ur - vr; xi[l] = ui - vi;
        }
    }
}

// ---------------- 256-pt FFT pass ----------------
#define FFT_SM 4352
__global__ void fft_pass2_kernel(const float2* __restrict__ cin,
                                 const float* __restrict__ rin,
                                 const float* __restrict__ fa,
                                 const float* __restrict__ fp,
                                 float2* __restrict__ cout,
                                 float* __restrict__ amp,
                                 float* __restrict__ ph,
                                 float* __restrict__ rout,
                                 int colmode, int dir, float scale) {
    __shared__ float sre[FFT_SM];
    __shared__ float sim[FFT_SM];
    int tid = threadIdx.x;
    int tx = tid & 15, ty = tid >> 4;
    int u = colmode ? ty : tx;
    int s = colmode ? tx : ty;
    int line = blockIdx.x * 16 + s;
    int plane = line >> 8, l = line & 255;
    long base; int stride;
    if (colmode) { base = (long)plane * 65536 + l; stride = 256; }
    else         { base = (long)plane * 65536 + (long)l * 256; stride = 1; }
    float dsign = (dir > 0) ? 1.f : -1.f;

    float xr[16], xi[16];
    #pragma unroll
    for (int n2 = 0; n2 < 16; n2++) {
        long a = base + (long)(u + 16 * n2) * stride;
        if (rin)      { xr[n2] = rin[a]; xi[n2] = 0.f; }
        else if (fa)  { float am = fa[a]; float sn, cs; sincosf(fp[a], &sn, &cs);
                        xr[n2] = am * cs; xi[n2] = am * sn; }
        else          { float2 c = cin[a]; xr[n2] = c.x; xi[n2] = c.y; }
    }
    fft16_reg(xr, xi, dsign);
    #pragma unroll
    for (int k2 = 0; k2 < 16; k2++) {
        int m = u * k2;
        float wr = g_t256r[m];
        float wi = dsign * g_t256i[m];
        float a = xr[k2], b = xi[k2];
        xr[k2] = a * wr - b * wi;
        xi[k2] = a * wi + b * wr;
    }
    #pragma unroll
    for (int k2 = 0; k2 < 16; k2++) {
        int idx = colmode ? ((k2 * 16 + u) * 17 + s) : (s * 272 + k2 * 17 + u);
        sre[idx] = xr[k2]; sim[idx] = xi[k2];
    }
    __syncthreads();
    #pragma unroll
    for (int n1 = 0; n1 < 16; n1++) {
        int idx = colmode ? ((u * 16 + n1) * 17 + s) : (s * 272 + u * 17 + n1);
        xr[n1] = sre[idx]; xi[n1] = sim[idx];
    }
    fft16_reg(xr, xi, dsign);
    #pragma unroll
    for (int k1 = 0; k1 < 16; k1++) {
        long a = base + (long)(16 * k1 + u) * stride;
        float rr = xr[k1] * scale, ii = xi[k1] * scale;
        if (cout)      cout[a] = make_float2(rr, ii);
        else if (amp)  { amp[a] = sqrtf(rr * rr + ii * ii); ph[a] = atan2f(ii, rr); }
        else           rout[a] = rr;
    }
}

// ---------------- router ----------------
__global__ void gap_kernel(const float* __restrict__ vis, const float* __restrict__ ir,
                           float* __restrict__ gm) {
    __shared__ float red[256];
    int b = blockIdx.x >> 7;
    int ch = blockIdx.x & 127;
    const float* p = (ch < 64) ? (vis + (long)(b * 64 + ch) * 65536)
                               : (ir  + (long)(b * 64 + ch - 64) * 65536);
    float s = 0.f;
    for (int i = threadIdx.x; i < 65536; i += 256) s += p[i];
    red[threadIdx.x] = s;
    __syncthreads();
    for (int st = 128; st > 0; st >>= 1) {
        if (threadIdx.x < st) red[threadIdx.x] += red[threadIdx.x + st];
        __syncthreads();
    }
    if (threadIdx.x == 0) gm[blockIdx.x] = red[0] * (1.0f / 65536.0f);
}

__global__ void router_kernel(const float* __restrict__ gm, const float* __restrict__ Wr,
                              const float* __restrict__ br, const float* __restrict__ bank,
                              float* __restrict__ intent) {
    __shared__ float pf[4][64];
    __shared__ float lg[4][4];
    __shared__ float w[4][4];
    int t = threadIdx.x;
    for (int b = 0; b < 4; b++) {
        float s = br[t];
        for (int c = 0; c < 128; c++) s += gm[b * 128 + c] * Wr[c * 64 + t];
        pf[b][t] = s;
    }
    __syncthreads();
    if (t < 16) {
        int b = t >> 2, j = t & 3;
        float s = 0.f;
        for (int p = 0; p < 64; p++) s += pf[b][p] * bank[j * 64 + p];
        lg[b][j] = s;
    }
    __syncthreads();
    if (t < 4) {
        int b = t;
        float m = fmaxf(fmaxf(lg[b][0], lg[b][1]), fmaxf(lg[b][2], lg[b][3]));
        float e0 = expf(lg[b][0] - m), e1 = expf(lg[b][1] - m);
        float e2 = expf(lg[b][2] - m), e3 = expf(lg[b][3] - m);
        float s = e0 + e1 + e2 + e3;
        w[b][0] = e0 / s; w[b][1] = e1 / s; w[b][2] = e2 / s; w[b][3] = e3 / s;
    }
    __syncthreads();
    for (int b = 0; b < 4; b++) {
        float s = 0.f;
        for (int j = 0; j < 4; j++) s += w[b][j] * bank[j * 64 + t];
        intent[b * 64 + t] = s;
    }
}

// ---------------- fused score net (R2 version: 64x128 tile, 4x8 micro) ----------------
__global__ void __launch_bounds__(256) score_fused_kernel(
        const float* __restrict__ mapV, const float* __restrict__ mapI,
        const float* __restrict__ intent,
        const float* __restrict__ W1, const float* __restrict__ b1,
        const float* __restrict__ W2, const float* __restrict__ b2,
        float* __restrict__ score) {
    const int BM = 64, BK = 16;
    __shared__ float As[BK][68];
    __shared__ float Bs[BK][132];
    __shared__ float red[64 * 16];
    int tid = threadIdx.x;
    int row0 = blockIdx.x * BM;
    int ty = tid >> 4, tx = tid & 15;

    float acc[4][8];
    #pragma unroll
    for (int i = 0; i < 4; i++)
        #pragma unroll
        for (int j = 0; j < 8; j++) acc[i][j] = 0.f;

    for (int k0 = 0; k0 < SF_; k0 += BK) {
        #pragma unroll
        for (int lq = 0; lq < 4; lq++) {
            int e = tid + lq * 256;
            int r = e >> 4, c = e & 15;
            int col = k0 + c;
            int tok = row0 + r;
            int b = tok >> 12, n = tok & 4095;
            float v = 0.f;
            if (col < 2048) {
                int t = col & 1023;
                int ch = t >> 4, py = (t >> 2) & 3, px = t & 3;
                int hy = n >> 6, wx = n & 63;
                long m = (((long)(b * 64 + ch) * 256) + hy * 4 + py) * 256 + wx * 4 + px;
                v = (col < 1024) ? mapV[m] : mapI[m];
            } else if (col < SF_) {
                if (col == 2048)      v = (float)(n >> 6) * (1.0f / 63.0f);
                else if (col == 2049) v = (float)(n & 63) * (1.0f / 63.0f);
                else                  v = intent[b * 64 + (col - 2050)];
            }
            As[c][r] = v;
        }
        #pragma unroll
        for (int lq = 0; lq < 8; lq++) {
            int e = tid + lq * 256;
            int r = e >> 7, c = e & 127;
            Bs[r][c] = (k0 + r < SF_) ? W1[(long)(k0 + r) * 128 + c] : 0.f;
        }
        __syncthreads();
        #pragma unroll
        for (int kk = 0; kk < BK; kk++) {
            float a[4], bb[8];
            float4 av = *(const float4*)&As[kk][ty * 4];
            a[0] = av.x; a[1] = av.y; a[2] = av.z; a[3] = av.w;
            float4 b0 = *(const float4*)&Bs[kk][tx * 8];
            float4 b1v = *(const float4*)&Bs[kk][tx * 8 + 4];
            bb[0] = b0.x; bb[1] = b0.y; bb[2] = b0.z; bb[3] = b0.w;
            bb[4] = b1v.x; bb[5] = b1v.y; bb[6] = b1v.z; bb[7] = b1v.w;
            #pragma unroll
            for (int i = 0; i < 4; i++)
                #pragma unroll
                for (int j = 0; j < 8; j++) acc[i][j] += a[i] * bb[j];
        }
        __syncthreads();
    }

    float w2[8], bs[8];
    #pragma unroll
    for (int j = 0; j < 8; j++) { w2[j] = W2[tx * 8 + j]; bs[j] = b1[tx * 8 + j]; }
    #pragma unroll
    for (int i = 0; i < 4; i++) {
        float p = 0.f;
        #pragma unroll
        for (int j = 0; j < 8; j++) {
            float h = fmaxf(acc[i][j] + bs[j], 0.f);
            p += h * w2[j];
        }
        red[(ty * 4 + i) * 16 + tx] = p;
    }
    __syncthreads();
    if (tid < 64) {
        float s = 0.f;
        #pragma unroll
        for (int q = 0; q < 16; q++) s += red[tid * 16 + q];
        score[row0 + tid] = s + b2[0];
    }
}

// ---------------- generic fp32 GEMM ----------------
__global__ void gemm_kernel(const float* __restrict__ A, const float* __restrict__ Bm,
                            float* __restrict__ C, const float* __restrict__ bias,
                            const float* __restrict__ residual,
                            int M, int N, int K, int act) {
    const int BM = 64, BN = 64, BK = 16;
    __shared__ float As[BK][BM];
    __shared__ float Bs[BK][BN + 1];
    int tid = threadIdx.x;
    int row0 = blockIdx.y * BM, col0 = blockIdx.x * BN;
    int ty = tid >> 4, tx = tid & 15;
    float acc[4][4];
    #pragma unroll
    for (int i = 0; i < 4; i++)
        #pragma unroll
        for (int j = 0; j < 4; j++) acc[i][j] = 0.f;

    for (int k0 = 0; k0 < K; k0 += BK) {
        #pragma unroll
        for (int l = 0; l < 4; l++) {
            int e = tid + l * 256;
            int r = e >> 4, c = e & 15;
            int gr = row0 + r, gc = k0 + c;
            As[c][r] = (gr < M && gc < K) ? A[(long)gr * K + gc] : 0.f;
        }
        #pragma unroll
        for (int l = 0; l < 4; l++) {
            int e = tid + l * 256;
            int r = e >> 6, c = e & 63;
            int gr = k0 + r, gc = col0 + c;
            Bs[r][c] = (gr < K && gc < N) ? Bm[(long)gr * N + gc] : 0.f;
        }
        __syncthreads();
        #pragma unroll
        for (int kk = 0; kk < BK; kk++) {
            float a[4], b[4];
            #pragma unroll
            for (int i = 0; i < 4; i++) a[i] = As[kk][ty * 4 + i];
            #pragma unroll
            for (int j = 0; j < 4; j++) b[j] = Bs[kk][tx * 4 + j];
            #pragma unroll
            for (int i = 0; i < 4; i++)
                #pragma unroll
                for (int j = 0; j < 4; j++) acc[i][j] += a[i] * b[j];
        }
        __syncthreads();
    }
    #pragma unroll
    for (int i = 0; i < 4; i++) {
        int r = row0 + ty * 4 + i;
        if (r >= M) continue;
        #pragma unroll
        for (int j = 0; j < 4; j++) {
            int c = col0 + tx * 4 + j;
            if (c >= N) continue;
            float v = acc[i][j];
            if (bias) v += bias[c];
            if (residual) v += residual[(long)r * N + c];
            if (act) v = fmaxf(v, 0.f);
            C[(long)r * N + c] = v;
        }
    }
}

// ---------------- top-k via bitonic sort ----------------
__global__ void __launch_bounds__(1024) topk_kernel(const float* __restrict__ score,
                                                    int* __restrict__ idxo) {
    __shared__ float key[4096];
    __shared__ int val[4096];
    int b = blockIdx.x;
    int t = threadIdx.x;
    for (int i = t; i < 4096; i += 1024) { key[i] = score[b * 4096 + i]; val[i] = i; }
    __syncthreads();
    for (int k = 2; k <= 4096; k <<= 1) {
        for (int j = k >> 1; j > 0; j >>= 1) {
            for (int i = t; i < 4096; i += 1024) {
                int ixj = i ^ j;
                if (ixj > i) {
                    bool desc = ((i & k) == 0);
                    float a = key[i], c = key[ixj];
                    bool sw = desc ? (a < c) : (a > c);
                    if (sw) {
                        key[i] = c; key[ixj] = a;
                        int tv = val[i]; val[i] = val[ixj]; val[ixj] = tv;
                    }
                }
            }
            __syncthreads();
        }
    }
    if (t < 1024) idxo[b * 1024 + t] = val[t];
}

// ---------------- gather / scatter ----------------
__device__ __forceinline__ long patch_pixel(int b, int n, int t) {
    int hy = n >> 6, wx = n & 63;
    int c = t >> 4, py = (t >> 2) & 3, px = t & 3;
    return (((long)(b * 64 + c) * 256) + hy * 4 + py) * 256 + wx * 4 + px;
}

__global__ void gather_kernel(const float* __restrict__ mapV, const float* __restrict__ mapI,
                              const int* __restrict__ idx,
                              float* __restrict__ selV, float* __restrict__ selI) {
    long gid = (long)blockIdx.x * 256 + threadIdx.x;
    int bi = (int)(gid >> 10);
    int t = (int)(gid & 1023);
    int b = bi >> 10;
    int n = idx[bi];
    long m = patch_pixel(b, n, t);
    selV[gid] = mapV[m];
    selI[gid] = mapI[m];
}

__global__ void scatter_kernel(const float* __restrict__ fs, const int* __restrict__ idx,
                               float* __restrict__ outMap) {
    long gid = (long)blockIdx.x * 256 + threadIdx.x;
    int bi = (int)(gid >> 10);
    int t = (int)(gid & 1023);
    int b = bi >> 10;
    int n = idx[bi];
    long m = patch_pixel(b, n, t);
    outMap[m] = fs[gid];
}

// ---------------- attention (R2 3-kernel pipeline) ----------------
__global__ void attn_scores_kernel(const float* __restrict__ Q, const float* __restrict__ Kt,
                                   float* __restrict__ S) {
    __shared__ float Qs[64][33];
    __shared__ float Ks[64][33];
    int z = blockIdx.z;
    int b = z >> 2, h = z & 3;
    const float* Qp = Q + (long)b * 1024 * 128 + h * 32;
    const float* Kp = Kt + (long)b * 1024 * 128 + h * 32;
    int i0 = blockIdx.y * 64, j0 = blockIdx.x * 64;
    int tid = threadIdx.x;
    #pragma unroll
    for (int l = 0; l < 8; l++) {
        int e = tid + l * 256;
        int r = e >> 5, c = e & 31;
        Qs[r][c] = Qp[(long)(i0 + r) * 128 + c];
        Ks[r][c] = Kp[(long)(j0 + r) * 128 + c];
    }
    __syncthreads();
    int ty = tid >> 4, tx = tid & 15;
    float acc[4][4];
    #pragma unroll
    for (int i = 0; i < 4; i++)
        #pragma unroll
        for (int j = 0; j < 4; j++) acc[i][j] = 0.f;
    #pragma unroll
    for (int d = 0; d < 32; d++) {
        float a[4], bb[4];
        #pragma unroll
        for (int i = 0; i < 4; i++) a[i] = Qs[ty * 4 + i][d];
        #pragma unroll
        for (int j = 0; j < 4; j++) bb[j] = Ks[tx * 4 + j][d];
        #pragma unroll
        for (int i = 0; i < 4; i++)
            #pragma unroll
            for (int j = 0; j < 4; j++) acc[i][j] += a[i] * bb[j];
    }
    const float scale = 0.17677669529663687f;
    #pragma unroll
    for (int i = 0; i < 4; i++)
        #pragma unroll
        for (int j = 0; j < 4; j++)
            S[((long)z * 1024 + i0 + ty * 4 + i) * 1024 + j0 + tx * 4 + j] = acc[i][j] * scale;
}

__global__ void softmax_kernel(float* __restrict__ S) {
    __shared__ float red[256];
    long base = ((long)blockIdx.y * 1024 + blockIdx.x) * 1024;
    int t = threadIdx.x;
    float v[4];
    float m = -3.4e38f;
    #pragma unroll
    for (int l = 0; l < 4; l++) { v[l] = S[base + t + l * 256]; m = fmaxf(m, v[l]); }
    red[t] = m;
    __syncthreads();
    for (int s = 128; s > 0; s >>= 1) {
        if (t < s) red[t] = fmaxf(red[t], red[t + s]);
        __syncthreads();
    }
    m = red[0];
    __syncthreads();
    float sum = 0.f;
    #pragma unroll
    for (int l = 0; l < 4; l++) { v[l] = __expf(v[l] - m); sum += v[l]; }
    red[t] = sum;
    __syncthreads();
    for (int s = 128; s > 0; s >>= 1) {
        if (t < s) red[t] += red[t + s];
        __syncthreads();
    }
    float inv = 1.0f / red[0];
    #pragma unroll
    for (int l = 0; l < 4; l++) S[base + t + l * 256] = v[l] * inv;
}

__global__ void attn_apply_kernel(const float* __restrict__ S, const float* __restrict__ V,
                                  float* __restrict__ O) {
    __shared__ float Ps[64][65];
    __shared__ float Vs[64][33];
    int z = blockIdx.y;
    int b = z >> 2, h = z & 3;
    int i0 = blockIdx.x * 64;
    int tid = threadIdx.x;
    int ty = tid >> 5, tx = tid & 31;
    float acc[8];
    #pragma unroll
    for (int q = 0; q < 8; q++) acc[q] = 0.f;
    for (int j0 = 0; j0 < 1024; j0 += 64) {
        #pragma unroll
        for (int l = 0; l < 16; l++) {
            int e = tid + l * 256;
            int r = e >> 6, c = e & 63;
            Ps[r][c] = S[((long)z * 1024 + i0 + r) * 1024 + j0 + c];
        }
        #pragma unroll
        for (int l = 0; l < 8; l++) {
            int e = tid + l * 256;
            int r = e >> 5, c = e & 31;
            Vs[r][c] = V[(long)(b * 1024 + j0 + r) * 128 + h * 32 + c];
        }
        __syncthreads();
        #pragma unroll
        for (int kk = 0; kk < 64; kk++) {
            float vv = Vs[kk][tx];
            #pragma unroll
            for (int q = 0; q < 8; q++) acc[q] += Ps[ty * 8 + q][kk] * vv;
        }
        __syncthreads();
    }
    #pragma unroll
    for (int q = 0; q < 8; q++)
        O[(long)(b * 1024 + i0 + ty * 8 + q) * 128 + h * 32 + tx] = acc[q];
}

// ---------------- elementwise avg ----------------
__global__ void avg_kernel(const float* __restrict__ a, const float* __restrict__ b,
                           float* __restrict__ o) {
    int i = blockIdx.x * 256 + threadIdx.x;
    o[i] = 0.5f * (a[i] + b[i]);
}

// ---------------- 3x3 SAME conv: 32x32 tile, 16 co/block, f32x2-packed 4 px/thread ----------------
__global__ void __launch_bounds__(256) conv3_kernel(
        const float* __restrict__ in, const float* __restrict__ wgt,
        const float* __restrict__ bias, float* __restrict__ out,
        const float* __restrict__ resA, const float* __restrict__ resB,
        int relu) {
    __shared__ float sIn[34][36];
    __shared__ float2 sW2[16][9];     // weight duplicated into both lanes
    int bz = blockIdx.z;
    int batch = bz >> 2, cg = bz & 3;
    int x0 = blockIdx.x * 32, y0 = blockIdx.y * 32;
    int tid = threadIdx.x;
    int tx = tid & 15, ty = tid >> 4;

    unsigned long long acc[16][2];
    #pragma unroll
    for (int co = 0; co < 16; co++) { acc[co][0] = 0ull; acc[co][1] = 0ull; }

    for (int ci = 0; ci < 64; ci++) {
        const float* ip = in + (long)(batch * 64 + ci) * 65536;
        for (int e = tid; e < 1156; e += 256) {
            int ry = e / 34, rx = e % 34;
            int gy = y0 + ry - 1, gx = x0 + rx - 1;
            sIn[ry][rx] = (gy >= 0 && gy < 256 && gx >= 0 && gx < 256) ? ip[gy * 256 + gx] : 0.f;
        }
        if (tid < 144) {
            int co = tid / 9, k = tid % 9;
            float w = wgt[((long)(cg * 16 + co) * 64 + ci) * 9 + k];
            sW2[co][k] = make_float2(w, w);
        }
        __syncthreads();

        // pack input pairs: lane0 = x, lane1 = x+16, for two row halves
        unsigned long long vp[2][9];
        #pragma unroll
        for (int a = 0; a < 2; a++)
            #pragma unroll
            for (int ky = 0; ky < 3; ky++)
                #pragma unroll
                for (int kx = 0; kx < 3; kx++)
                    vp[a][ky * 3 + kx] = pk2(sIn[ty + a * 16 + ky][tx + kx],
                                             sIn[ty + a * 16 + ky][tx + 16 + kx]);
        #pragma unroll
        for (int co = 0; co < 16; co++) {
            #pragma unroll
            for (int k = 0; k < 9; k++) {
                unsigned long long w2 = *(const unsigned long long*)&sW2[co][k];
                FMA2_(acc[co][0], vp[0][k], w2);
                FMA2_(acc[co][1], vp[1][k], w2);
            }
        }
        __syncthreads();
    }
    #pragma unroll
    for (int co = 0; co < 16; co++) {
        int gco = cg * 16 + co;
        float bsv = bias[gco];
        #pragma unroll
        for (int a = 0; a < 2; a++) {
            float p0, p1;
            upk2(acc[co][a], p0, p1);
            int y = y0 + ty + a * 16;
            long o0 = ((long)(batch * 64 + gco) * 256 + y) * 256 + x0 + tx;
            long o1 = o0 + 16;
            float v0 = p0 + bsv, v1 = p1 + bsv;
            if (relu) { v0 = fmaxf(v0, 0.f); v1 = fmaxf(v1, 0.f); }
            if (resA) {
                v0 += 0.5f * (resA[o0] + resB[o0]);
                v1 += 0.5f * (resA[o1] + resB[o1]);
            }
            out[o0] = v0;
            out[o1] = v1;
        }
    }
}

// ---------------- host-side branch driver ----------------
static void run_branch(const float* mapV, const float* mapI,
                       const float* W1, const float* b1,
                       const float* W2, const float* b2,
                       const float* Wq, const float* Wk, const float* Wv, const float* Wo,
                       const float* intent,
                       float* score, int* idxp,
                       float* selV, float* selI,
                       float* q, float* k, float* v, float* o,
                       float* att, float* fs, float* outMap) {
    score_fused_kernel<<<256, 256>>>(mapV, mapI, intent, W1, b1, W2, b2, score);
    topk_kernel<<<4, 1024>>>(score, idxp);
    gather_kernel<<<16384, 256>>>(mapV, mapI, idxp, selV, selI);
    gemm_kernel<<<dim3(2, 64), 256>>>(selV, Wq, q, nullptr, nullptr, 4096, 128, 1024, 0);
    gemm_kernel<<<dim3(2, 64), 256>>>(selI, Wk, k, nullptr, nullptr, 4096, 128, 1024, 0);
    gemm_kernel<<<dim3(2, 64), 256>>>(selI, Wv, v, nullptr, nullptr, 4096, 128, 1024, 0);
    attn_scores_kernel<<<dim3(16, 16, 16), 256>>>(q, k, att);
    softmax_kernel<<<dim3(1024, 16), 256>>>(att);
    attn_apply_kernel<<<dim3(16, 16), 256>>>(att, v, o);
    gemm_kernel<<<dim3(16, 64), 256>>>(o, Wo, fs, nullptr, selV, 4096, 1024, 128, 0);
    avg_kernel<<<65536, 256>>>(mapV, mapI, outMap);
    scatter_kernel<<<16384, 256>>>(fs, idxp, outMap);
}

extern "C" void kernel_launch(void* const* d_in, const int* in_sizes, int n_in,
                              void* d_out, int out_size) {
    const float* vis  = (const float*)d_in[0];
    const float* ir   = (const float*)d_in[1];
    const float* bank = (const float*)d_in[2];
    const float* Wr   = (const float*)d_in[3];
    const float* br   = (const float*)d_in[4];
    const float* aW1  = (const float*)d_in[5];
    const float* ab1  = (const float*)d_in[6];
    const float* aW2  = (const float*)d_in[7];
    const float* ab2  = (const float*)d_in[8];
    const float* aWq  = (const float*)d_in[9];
    const float* aWk  = (const float*)d_in[10];
    const float* aWv  = (const float*)d_in[11];
    const float* aWo  = (const float*)d_in[12];
    const float* pW1  = (const float*)d_in[13];
    const float* pb1  = (const float*)d_in[14];
    const float* pW2  = (const float*)d_in[15];
    const float* pb2  = (const float*)d_in[16];
    const float* pWq  = (const float*)d_in[17];
    const float* pWk  = (const float*)d_in[18];
    const float* pWv  = (const float*)d_in[19];
    const float* pWo  = (const float*)d_in[20];
    const float* c1w  = (const float*)d_in[21];
    const float* c1b  = (const float*)d_in[22];
    const float* c2w  = (const float*)d_in[23];
    const float* c2b  = (const float*)d_in[24];
    float* out = (float*)d_out;

    float2* cA;
    float *ampV, *ampI, *phV, *phI, *faMap, *fpMap, *spatial, *r1;
    float *score, *selV, *selI, *q, *k, *v, *o, *att, *fs, *gm, *intent;
    int* idxp;
    cudaGetSymbolAddress((void**)&cA, g_cA);
    cudaGetSymbolAddress((void**)&ampV, g_ampV);
    cudaGetSymbolAddress((void**)&ampI, g_ampI);
    cudaGetSymbolAddress((void**)&phV, g_phV);
    cudaGetSymbolAddress((void**)&phI, g_phI);
    cudaGetSymbolAddress((void**)&faMap, g_faMap);
    cudaGetSymbolAddress((void**)&fpMap, g_fpMap);
    cudaGetSymbolAddress((void**)&spatial, g_spatial);
    cudaGetSymbolAddress((void**)&r1, g_r1);
    cudaGetSymbolAddress((void**)&score, g_scoreArr);
    cudaGetSymbolAddress((void**)&idxp, g_idxArr);
    cudaGetSymbolAddress((void**)&selV, g_selV);
    cudaGetSymbolAddress((void**)&selI, g_selI);
    cudaGetSymbolAddress((void**)&q, g_qb);
    cudaGetSymbolAddress((void**)&k, g_kb);
    cudaGetSymbolAddress((void**)&v, g_vb);
    cudaGetSymbolAddress((void**)&o, g_ob);
    cudaGetSymbolAddress((void**)&att, g_att);
    cudaGetSymbolAddress((void**)&fs, g_fs);
    cudaGetSymbolAddress((void**)&gm, g_gm);
    cudaGetSymbolAddress((void**)&intent, g_intentArr);

    twiddle_init_kernel<<<1, 256>>>();
    gap_kernel<<<512, 256>>>(vis, ir, gm);
    router_kernel<<<1, 64>>>(gm, Wr, br, bank, intent);

    const int FB = 4096;
    fft_pass2_kernel<<<FB, 256>>>(nullptr, vis, nullptr, nullptr, cA, nullptr, nullptr, nullptr, 0, +1, 1.f);
    fft_pass2_kernel<<<FB, 256>>>(cA, nullptr, nullptr, nullptr, nullptr, ampV, phV, nullptr, 1, +1, 1.f);
    fft_pass2_kernel<<<FB, 256>>>(nullptr, ir, nullptr, nullptr, cA, nullptr, nullptr, nullptr, 0, +1, 1.f);
    fft_pass2_kernel<<<FB, 256>>>(cA, nullptr, nullptr, nullptr, nullptr, ampI, phI, nullptr, 1, +1, 1.f);

    run_branch(ampV, ampI, aW1, ab1, aW2, ab2, aWq, aWk, aWv, aWo, intent,
               score, idxp, selV, selI, q, k, v, o, att, fs, faMap);
    run_branch(phV, phI, pW1, pb1, pW2, pb2, pWq, pWk, pWv, pWo, intent,
               score, idxp, selV, selI, q, k, v, o, att, fs, fpMap);

    fft_pass2_kernel<<<FB, 256>>>(nullptr, nullptr, faMap, fpMap, cA, nullptr, nullptr, nullptr, 0, -1, 1.f);
    fft_pass2_kernel<<<FB, 256>>>(cA, nullptr, nullptr, nullptr, nullptr, nullptr, nullptr, spatial, 1, -1, 1.0f / 65536.0f);

    conv3_kernel<<<dim3(8, 8, 16), 256>>>(spatial, c1w, c1b, r1, nullptr, nullptr, 1);
    conv3_kernel<<<dim3(8, 8, 16), 256>>>(r1, c2w, c2b, out, vis, ir, 0);

    (void)in_sizes; (void)n_in; (void)out_size;
}

// round 5
// speedup vs baseline: 1.1620x; 1.1358x over previous
#include <cuda_runtime.h>
#include <math.h>

// ---------------- problem constants ----------------
#define B_    4
#define C_    64
#define NPIX_ 16777216            // B*C*H*W
#define NT_   16384               // B * NPAT
#define TOK_  1024
#define SF_   2114
#define KSEL_ 1024
#define E_    128

// ---------------- device scratch ----------------
__device__ float2 g_cA[NPIX_];
__device__ float  g_ampV[NPIX_];
__device__ float  g_ampI[NPIX_];
__device__ float  g_phV [NPIX_];
__device__ float  g_phI [NPIX_];
__device__ float  g_faMap[NPIX_];
__device__ float  g_fpMap[NPIX_];
__device__ float  g_spatial[NPIX_];
__device__ float  g_r1[NPIX_];
__device__ float  g_scoreArr[NT_];
__device__ int    g_idxArr[B_ * KSEL_];
__device__ float  g_selV[(long)B_ * KSEL_ * TOK_];
__device__ float  g_selI[(long)B_ * KSEL_ * TOK_];
__device__ float  g_qb[B_ * KSEL_ * E_];
__device__ float  g_kb[B_ * KSEL_ * E_];
__device__ float  g_vb[B_ * KSEL_ * E_];
__device__ float  g_ob[B_ * KSEL_ * E_];
__device__ float  g_att[(long)B_ * 4 * KSEL_ * KSEL_];
__device__ float  g_fs[(long)B_ * KSEL_ * TOK_];
__device__ float  g_gm[B_ * 2 * C_];
__device__ float  g_intentArr[B_ * 64];
__device__ float  g_t256r[256];
__device__ float  g_t256i[256];

// ---------------- packed f32x2 helpers (sm_103a FFMA2) ----------------
__device__ __forceinline__ unsigned long long pk2(float lo, float hi) {
    unsigned long long r;
    asm("mov.b64 %0, {%1, %2};" : "=l"(r) : "f"(lo), "f"(hi));
    return r;
}
__device__ __forceinline__ void upk2(unsigned long long v, float& lo, float& hi) {
    asm("mov.b64 {%0, %1}, %2;" : "=f"(lo), "=f"(hi) : "l"(v));
}
#define FMA2_(d, a, b) asm("fma.rn.f32x2 %0, %1, %2, %0;" : "+l"(d) : "l"(a), "l"(b))

// ---------------- twiddles ----------------
__global__ void twiddle_init_kernel() {
    int k = threadIdx.x;
    double a = -2.0 * 3.14159265358979323846 * (double)k / 256.0;
    g_t256r[k] = (float)cos(a);
    g_t256i[k] = (float)sin(a);
}

// ---------------- 16-point register FFT ----------------
__device__ __forceinline__ void fft16_reg(float* xr, float* xi, float dsign) {
    #define SW16_(a,b) { float t=xr[a]; xr[a]=xr[b]; xr[b]=t; t=xi[a]; xi[a]=xi[b]; xi[b]=t; }
    SW16_(1,8) SW16_(2,4) SW16_(3,12) SW16_(5,10) SW16_(7,14) SW16_(11,13)
    #undef SW16_
    const float C16[8] = {1.f, 0.9238795325112867f, 0.7071067811865476f, 0.3826834323650898f,
                          0.f, -0.3826834323650898f, -0.7071067811865476f, -0.9238795325112867f};
    const float S16[8] = {0.f, 0.3826834323650898f, 0.7071067811865476f, 0.9238795325112867f,
                          1.f, 0.9238795325112867f, 0.7071067811865476f, 0.3826834323650898f};
    #pragma unroll
    for (int s = 1; s <= 4; s++) {
        const int half = 1 << (s - 1);
        #pragma unroll
        for (int j = 0; j < 8; j++) {
            const int grp = j >> (s - 1);
            const int pos = j & (half - 1);
            const int i = (grp << s) + pos;
            const int l = i + half;
            const int ti = pos << (4 - s);
            float wr = C16[ti];
            float wi = -dsign * S16[ti];
            float vr = xr[l] * wr - xi[l] * wi;
            float vi = xr[l] * wi + xi[l] * wr;
            float ur = xr[i], ui = xi[i];
            xr[i] = ur + vr; xi[i] = ui + vi;
            xr[l] = ur - vr; xi[l] = ui - vi;
        }
    }
}

// ---------------- 256-pt FFT pass ----------------
#define FFT_SM 4352
__global__ void fft_pass2_kernel(const float2* __restrict__ cin,
                                 const float* __restrict__ rin,
                                 const float* __restrict__ fa,
                                 const float* __restrict__ fp,
                                 float2* __restrict__ cout,
                                 float* __restrict__ amp,
                                 float* __restrict__ ph,
                                 float* __restrict__ rout,
                                 int colmode, int dir, float scale) {
    __shared__ float sre[FFT_SM];
    __shared__ float sim[FFT_SM];
    int tid = threadIdx.x;
    int tx = tid & 15, ty = tid >> 4;
    int u = colmode ? ty : tx;
    int s = colmode ? tx : ty;
    int line = blockIdx.x * 16 + s;
    int plane = line >> 8, l = line & 255;
    long base; int stride;
    if (colmode) { base = (long)plane * 65536 + l; stride = 256; }
    else         { base = (long)plane * 65536 + (long)l * 256; stride = 1; }
    float dsign = (dir > 0) ? 1.f : -1.f;

    float xr[16], xi[16];
    #pragma unroll
    for (int n2 = 0; n2 < 16; n2++) {
        long a = base + (long)(u + 16 * n2) * stride;
        if (rin)      { xr[n2] = rin[a]; xi[n2] = 0.f; }
        else if (fa)  { float am = fa[a]; float sn, cs; sincosf(fp[a], &sn, &cs);
                        xr[n2] = am * cs; xi[n2] = am * sn; }
        else          { float2 c = cin[a]; xr[n2] = c.x; xi[n2] = c.y; }
    }
    fft16_reg(xr, xi, dsign);
    #pragma unroll
    for (int k2 = 0; k2 < 16; k2++) {
        int m = u * k2;
        float wr = g_t256r[m];
        float wi = dsign * g_t256i[m];
        float a = xr[k2], b = xi[k2];
        xr[k2] = a * wr - b * wi;
        xi[k2] = a * wi + b * wr;
    }
    #pragma unroll
    for (int k2 = 0; k2 < 16; k2++) {
        int idx = colmode ? ((k2 * 16 + u) * 17 + s) : (s * 272 + k2 * 17 + u);
        sre[idx] = xr[k2]; sim[idx] = xi[k2];
    }
    __syncthreads();
    #pragma unroll
    for (int n1 = 0; n1 < 16; n1++) {
        int idx = colmode ? ((u * 16 + n1) * 17 + s) : (s * 272 + u * 17 + n1);
        xr[n1] = sre[idx]; xi[n1] = sim[idx];
    }
    fft16_reg(xr, xi, dsign);
    #pragma unroll
    for (int k1 = 0; k1 < 16; k1++) {
        long a = base + (long)(16 * k1 + u) * stride;
        float rr = xr[k1] * scale, ii = xi[k1] * scale;
        if (cout)      cout[a] = make_float2(rr, ii);
        else if (amp)  { amp[a] = sqrtf(rr * rr + ii * ii); ph[a] = atan2f(ii, rr); }
        else           rout[a] = rr;
    }
}

// ---------------- router ----------------
__global__ void gap_kernel(const float* __restrict__ vis, const float* __restrict__ ir,
                           float* __restrict__ gm) {
    __shared__ float red[256];
    int b = blockIdx.x >> 7;
    int ch = blockIdx.x & 127;
    const float* p = (ch < 64) ? (vis + (long)(b * 64 + ch) * 65536)
                               : (ir  + (long)(b * 64 + ch - 64) * 65536);
    float s = 0.f;
    for (int i = threadIdx.x; i < 65536; i += 256) s += p[i];
    red[threadIdx.x] = s;
    __syncthreads();
    for (int st = 128; st > 0; st >>= 1) {
        if (threadIdx.x < st) red[threadIdx.x] += red[threadIdx.x + st];
        __syncthreads();
    }
    if (threadIdx.x == 0) gm[blockIdx.x] = red[0] * (1.0f / 65536.0f);
}

__global__ void router_kernel(const float* __restrict__ gm, const float* __restrict__ Wr,
                              const float* __restrict__ br, const float* __restrict__ bank,
                              float* __restrict__ intent) {
    __shared__ float pf[4][64];
    __shared__ float lg[4][4];
    __shared__ float w[4][4];
    int t = threadIdx.x;
    for (int b = 0; b < 4; b++) {
        float s = br[t];
        for (int c = 0; c < 128; c++) s += gm[b * 128 + c] * Wr[c * 64 + t];
        pf[b][t] = s;
    }
    __syncthreads();
    if (t < 16) {
        int b = t >> 2, j = t & 3;
        float s = 0.f;
        for (int p = 0; p < 64; p++) s += pf[b][p] * bank[j * 64 + p];
        lg[b][j] = s;
    }
    __syncthreads();
    if (t < 4) {
        int b = t;
        float m = fmaxf(fmaxf(lg[b][0], lg[b][1]), fmaxf(lg[b][2], lg[b][3]));
        float e0 = expf(lg[b][0] - m), e1 = expf(lg[b][1] - m);
        float e2 = expf(lg[b][2] - m), e3 = expf(lg[b][3] - m);
        float s = e0 + e1 + e2 + e3;
        w[b][0] = e0 / s; w[b][1] = e1 / s; w[b][2] = e2 / s; w[b][3] = e3 / s;
    }
    __syncthreads();
    for (int b = 0; b < 4; b++) {
        float s = 0.f;
        for (int j = 0; j < 4; j++) s += w[b][j] * bank[j * 64 + t];
        intent[b * 64 + t] = s;
    }
}

// ---------------- fused score net (R2 version: 64x128 tile, 4x8 micro) ----------------
__global__ void __launch_bounds__(256) score_fused_kernel(
        const float* __restrict__ mapV, const float* __restrict__ mapI,
        const float* __restrict__ intent,
        const float* __restrict__ W1, const float* __restrict__ b1,
        const float* __restrict__ W2, const float* __restrict__ b2,
        float* __restrict__ score) {
    const int BM = 64, BK = 16;
    __shared__ float As[BK][68];
    __shared__ float Bs[BK][132];
    __shared__ float red[64 * 16];
    int tid = threadIdx.x;
    int row0 = blockIdx.x * BM;
    int ty = tid >> 4, tx = tid & 15;

    float acc[4][8];
    #pragma unroll
    for (int i = 0; i < 4; i++)
        #pragma unroll
        for (int j = 0; j < 8; j++) acc[i][j] = 0.f;

    for (int k0 = 0; k0 < SF_; k0 += BK) {
        #pragma unroll
        for (int lq = 0; lq < 4; lq++) {
            int e = tid + lq * 256;
            int r = e >> 4, c = e & 15;
            int col = k0 + c;
            int tok = row0 + r;
            int b = tok >> 12, n = tok & 4095;
            float v = 0.f;
            if (col < 2048) {
                int t = col & 1023;
                int ch = t >> 4, py = (t >> 2) & 3, px = t & 3;
                int hy = n >> 6, wx = n & 63;
                long m = (((long)(b * 64 + ch) * 256) + hy * 4 + py) * 256 + wx * 4 + px;
                v = (col < 1024) ? mapV[m] : mapI[m];
            } else if (col < SF_) {
                if (col == 2048)      v = (float)(n >> 6) * (1.0f / 63.0f);
                else if (col == 2049) v = (float)(n & 63) * (1.0f / 63.0f);
                else                  v = intent[b * 64 + (col - 2050)];
            }
            As[c][r] = v;
        }
        #pragma unroll
        for (int lq = 0; lq < 8; lq++) {
            int e = tid + lq * 256;
            int r = e >> 7, c = e & 127;
            Bs[r][c] = (k0 + r < SF_) ? W1[(long)(k0 + r) * 128 + c] : 0.f;
        }
        __syncthreads();
        #pragma unroll
        for (int kk = 0; kk < BK; kk++) {
            float a[4], bb[8];
            float4 av = *(const float4*)&As[kk][ty * 4];
            a[0] = av.x; a[1] = av.y; a[2] = av.z; a[3] = av.w;
            float4 b0 = *(const float4*)&Bs[kk][tx * 8];
            float4 b1v = *(const float4*)&Bs[kk][tx * 8 + 4];
            bb[0] = b0.x; bb[1] = b0.y; bb[2] = b0.z; bb[3] = b0.w;
            bb[4] = b1v.x; bb[5] = b1v.y; bb[6] = b1v.z; bb[7] = b1v.w;
            #pragma unroll
            for (int i = 0; i < 4; i++)
                #pragma unroll
                for (int j = 0; j < 8; j++) acc[i][j] += a[i] * bb[j];
        }
        __syncthreads();
    }

    float w2[8], bs[8];
    #pragma unroll
    for (int j = 0; j < 8; j++) { w2[j] = W2[tx * 8 + j]; bs[j] = b1[tx * 8 + j]; }
    #pragma unroll
    for (int i = 0; i < 4; i++) {
        float p = 0.f;
        #pragma unroll
        for (int j = 0; j < 8; j++) {
            float h = fmaxf(acc[i][j] + bs[j], 0.f);
            p += h * w2[j];
        }
        red[(ty * 4 + i) * 16 + tx] = p;
    }
    __syncthreads();
    if (tid < 64) {
        float s = 0.f;
        #pragma unroll
        for (int q = 0; q < 16; q++) s += red[tid * 16 + q];
        score[row0 + tid] = s + b2[0];
    }
}

// ---------------- generic fp32 GEMM ----------------
__global__ void gemm_kernel(const float* __restrict__ A, const float* __restrict__ Bm,
                            float* __restrict__ C, const float* __restrict__ bias,
                            const float* __restrict__ residual,
                            int M, int N, int K, int act) {
    const int BM = 64, BN = 64, BK = 16;
    __shared__ float As[BK][BM];
    __shared__ float Bs[BK][BN + 1];
    int tid = threadIdx.x;
    int row0 = blockIdx.y * BM, col0 = blockIdx.x * BN;
    int ty = tid >> 4, tx = tid & 15;
    float acc[4][4];
    #pragma unroll
    for (int i = 0; i < 4; i++)
        #pragma unroll
        for (int j = 0; j < 4; j++) acc[i][j] = 0.f;

    for (int k0 = 0; k0 < K; k0 += BK) {
        #pragma unroll
        for (int l = 0; l < 4; l++) {
            int e = tid + l * 256;
            int r = e >> 4, c = e & 15;
            int gr = row0 + r, gc = k0 + c;
            As[c][r] = (gr < M && gc < K) ? A[(long)gr * K + gc] : 0.f;
        }
        #pragma unroll
        for (int l = 0; l < 4; l++) {
            int e = tid + l * 256;
            int r = e >> 6, c = e & 63;
            int gr = k0 + r, gc = col0 + c;
            Bs[r][c] = (gr < K && gc < N) ? Bm[(long)gr * N + gc] : 0.f;
        }
        __syncthreads();
        #pragma unroll
        for (int kk = 0; kk < BK; kk++) {
            float a[4], b[4];
            #pragma unroll
            for (int i = 0; i < 4; i++) a[i] = As[kk][ty * 4 + i];
            #pragma unroll
            for (int j = 0; j < 4; j++) b[j] = Bs[kk][tx * 4 + j];
            #pragma unroll
            for (int i = 0; i < 4; i++)
                #pragma unroll
                for (int j = 0; j < 4; j++) acc[i][j] += a[i] * b[j];
        }
        __syncthreads();
    }
    #pragma unroll
    for (int i = 0; i < 4; i++) {
        int r = row0 + ty * 4 + i;
        if (r >= M) continue;
        #pragma unroll
        for (int j = 0; j < 4; j++) {
            int c = col0 + tx * 4 + j;
            if (c >= N) continue;
            float v = acc[i][j];
            if (bias) v += bias[c];
            if (residual) v += residual[(long)r * N + c];
            if (act) v = fmaxf(v, 0.f);
            C[(long)r * N + c] = v;
        }
    }
}

// ---------------- top-k via bitonic sort ----------------
__global__ void __launch_bounds__(1024) topk_kernel(const float* __restrict__ score,
                                                    int* __restrict__ idxo) {
    __shared__ float key[4096];
    __shared__ int val[4096];
    int b = blockIdx.x;
    int t = threadIdx.x;
    for (int i = t; i < 4096; i += 1024) { key[i] = score[b * 4096 + i]; val[i] = i; }
    __syncthreads();
    for (int k = 2; k <= 4096; k <<= 1) {
        for (int j = k >> 1; j > 0; j >>= 1) {
            for (int i = t; i < 4096; i += 1024) {
                int ixj = i ^ j;
                if (ixj > i) {
                    bool desc = ((i & k) == 0);
                    float a = key[i], c = key[ixj];
                    bool sw = desc ? (a < c) : (a > c);
                    if (sw) {
                        key[i] = c; key[ixj] = a;
                        int tv = val[i]; val[i] = val[ixj]; val[ixj] = tv;
                    }
                }
            }
            __syncthreads();
        }
    }
    if (t < 1024) idxo[b * 1024 + t] = val[t];
}

// ---------------- gather / scatter ----------------
__device__ __forceinline__ long patch_pixel(int b, int n, int t) {
    int hy = n >> 6, wx = n & 63;
    int c = t >> 4, py = (t >> 2) & 3, px = t & 3;
    return (((long)(b * 64 + c) * 256) + hy * 4 + py) * 256 + wx * 4 + px;
}

__global__ void gather_kernel(const float* __restrict__ mapV, const float* __restrict__ mapI,
                              const int* __restrict__ idx,
                              float* __restrict__ selV, float* __restrict__ selI) {
    long gid = (long)blockIdx.x * 256 + threadIdx.x;
    int bi = (int)(gid >> 10);
    int t = (int)(gid & 1023);
    int b = bi >> 10;
    int n = idx[bi];
    long m = patch_pixel(b, n, t);
    selV[gid] = mapV[m];
    selI[gid] = mapI[m];
}

__global__ void scatter_kernel(const float* __restrict__ fs, const int* __restrict__ idx,
                               float* __restrict__ outMap) {
    long gid = (long)blockIdx.x * 256 + threadIdx.x;
    int bi = (int)(gid >> 10);
    int t = (int)(gid & 1023);
    int b = bi >> 10;
    int n = idx[bi];
    long m = patch_pixel(b, n, t);
    outMap[m] = fs[gid];
}

// ---------------- attention (3-kernel pipeline) ----------------
__global__ void attn_scores_kernel(const float* __restrict__ Q, const float* __restrict__ Kt,
                                   float* __restrict__ S) {
    __shared__ float Qs[64][33];
    __shared__ float Ks[64][33];
    int z = blockIdx.z;
    int b = z >> 2, h = z & 3;
    const float* Qp = Q + (long)b * 1024 * 128 + h * 32;
    const float* Kp = Kt + (long)b * 1024 * 128 + h * 32;
    int i0 = blockIdx.y * 64, j0 = blockIdx.x * 64;
    int tid = threadIdx.x;
    #pragma unroll
    for (int l = 0; l < 8; l++) {
        int e = tid + l * 256;
        int r = e >> 5, c = e & 31;
        Qs[r][c] = Qp[(long)(i0 + r) * 128 + c];
        Ks[r][c] = Kp[(long)(j0 + r) * 128 + c];
    }
    __syncthreads();
    int ty = tid >> 4, tx = tid & 15;
    float acc[4][4];
    #pragma unroll
    for (int i = 0; i < 4; i++)
        #pragma unroll
        for (int j = 0; j < 4; j++) acc[i][j] = 0.f;
    #pragma unroll
    for (int d = 0; d < 32; d++) {
        float a[4], bb[4];
        #pragma unroll
        for (int i = 0; i < 4; i++) a[i] = Qs[ty * 4 + i][d];
        #pragma unroll
        for (int j = 0; j < 4; j++) bb[j] = Ks[tx * 4 + j][d];
        #pragma unroll
        for (int i = 0; i < 4; i++)
            #pragma unroll
            for (int j = 0; j < 4; j++) acc[i][j] += a[i] * bb[j];
    }
    const float scale = 0.17677669529663687f;
    #pragma unroll
    for (int i = 0; i < 4; i++)
        #pragma unroll
        for (int j = 0; j < 4; j++)
            S[((long)z * 1024 + i0 + ty * 4 + i) * 1024 + j0 + tx * 4 + j] = acc[i][j] * scale;
}

__global__ void softmax_kernel(float* __restrict__ S) {
    __shared__ float red[256];
    long base = ((long)blockIdx.y * 1024 + blockIdx.x) * 1024;
    int t = threadIdx.x;
    float v[4];
    float m = -3.4e38f;
    #pragma unroll
    for (int l = 0; l < 4; l++) { v[l] = S[base + t + l * 256]; m = fmaxf(m, v[l]); }
    red[t] = m;
    __syncthreads();
    for (int s = 128; s > 0; s >>= 1) {
        if (t < s) red[t] = fmaxf(red[t], red[t + s]);
        __syncthreads();
    }
    m = red[0];
    __syncthreads();
    float sum = 0.f;
    #pragma unroll
    for (int l = 0; l < 4; l++) { v[l] = __expf(v[l] - m); sum += v[l]; }
    red[t] = sum;
    __syncthreads();
    for (int s = 128; s > 0; s >>= 1) {
        if (t < s) red[t] += red[t + s];
        __syncthreads();
    }
    float inv = 1.0f / red[0];
    #pragma unroll
    for (int l = 0; l < 4; l++) S[base + t + l * 256] = v[l] * inv;
}

__global__ void attn_apply_kernel(const float* __restrict__ S, const float* __restrict__ V,
                                  float* __restrict__ O) {
    __shared__ float Ps[64][65];
    __shared__ float Vs[64][33];
    int z = blockIdx.y;
    int b = z >> 2, h = z & 3;
    int i0 = blockIdx.x * 64;
    int tid = threadIdx.x;
    int ty = tid >> 5, tx = tid & 31;
    float acc[8];
    #pragma unroll
    for (int q = 0; q < 8; q++) acc[q] = 0.f;
    for (int j0 = 0; j0 < 1024; j0 += 64) {
        #pragma unroll
        for (int l = 0; l < 16; l++) {
            int e = tid + l * 256;
            int r = e >> 6, c = e & 63;
            Ps[r][c] = S[((long)z * 1024 + i0 + r) * 1024 + j0 + c];
        }
        #pragma unroll
        for (int l = 0; l < 8; l++) {
            int e = tid + l * 256;
            int r = e >> 5, c = e & 31;
            Vs[r][c] = V[(long)(b * 1024 + j0 + r) * 128 + h * 32 + c];
        }
        __syncthreads();
        #pragma unroll
        for (int kk = 0; kk < 64; kk++) {
            float vv = Vs[kk][tx];
            #pragma unroll
            for (int q = 0; q < 8; q++) acc[q] += Ps[ty * 8 + q][kk] * vv;
        }
        __syncthreads();
    }
    #pragma unroll
    for (int q = 0; q < 8; q++)
        O[(long)(b * 1024 + i0 + ty * 8 + q) * 128 + h * 32 + tx] = acc[q];
}

// ---------------- elementwise avg ----------------
__global__ void avg_kernel(const float* __restrict__ a, const float* __restrict__ b,
                           float* __restrict__ o) {
    int i = blockIdx.x * 256 + threadIdx.x;
    o[i] = 0.5f * (a[i] + b[i]);
}

// ---------------- 3x3 SAME conv: 16x16 tile, 64 co/block, channel-pair FMA2 ----------------
__global__ void __launch_bounds__(256) conv3_kernel(
        const float* __restrict__ in, const float* __restrict__ wgt,
        const float* __restrict__ bias, float* __restrict__ out,
        const float* __restrict__ resA, const float* __restrict__ resB,
        int relu) {
    __shared__ float sIn[18][18];
    __shared__ float2 sW2[32][9];   // co-pair packed weights: {w[2p][k], w[2p+1][k]}
    int bz = blockIdx.z;
    int x0 = blockIdx.x * 16, y0 = blockIdx.y * 16;
    int tx = threadIdx.x & 15, ty = threadIdx.x >> 4;
    int tid = threadIdx.x;
    int x = x0 + tx, y = y0 + ty;

    unsigned long long acc[32];
    #pragma unroll
    for (int p = 0; p < 32; p++) acc[p] = 0ull;

    for (int ci = 0; ci < 64; ci++) {
        const float* ip = in + (long)(bz * 64 + ci) * 65536;
        for (int e = tid; e < 324; e += 256) {
            int ry = e / 18, rx = e % 18;
            int gy = y0 + ry - 1, gx = x0 + rx - 1;
            sIn[ry][rx] = (gy >= 0 && gy < 256 && gx >= 0 && gx < 256) ? ip[gy * 256 + gx] : 0.f;
        }
        for (int e = tid; e < 288; e += 256) {
            int p = e / 9, k = e % 9;
            sW2[p][k] = make_float2(wgt[((long)(2 * p) * 64 + ci) * 9 + k],
                                    wgt[((long)(2 * p + 1) * 64 + ci) * 9 + k]);
        }
        __syncthreads();
        // 9 input taps, duplicated into both lanes
        unsigned long long vp[9];
        #pragma unroll
        for (int ky = 0; ky < 3; ky++)
            #pragma unroll
            for (int kx = 0; kx < 3; kx++) {
                float v = sIn[ty + ky][tx + kx];
                vp[ky * 3 + kx] = pk2(v, v);
            }
        #pragma unroll
        for (int p = 0; p < 32; p++) {
            #pragma unroll
            for (int k = 0; k < 9; k++) {
                unsigned long long w2 = *(const unsigned long long*)&sW2[p][k];
                FMA2_(acc[p], vp[k], w2);
            }
        }
        __syncthreads();
    }
    #pragma unroll
    for (int p = 0; p < 32; p++) {
        float v0, v1;
        upk2(acc[p], v0, v1);
        int co0 = 2 * p, co1 = 2 * p + 1;
        long o0 = ((long)(bz * 64 + co0) * 256 + y) * 256 + x;
        long o1 = ((long)(bz * 64 + co1) * 256 + y) * 256 + x;
        v0 += bias[co0];
        v1 += bias[co1];
        if (relu) { v0 = fmaxf(v0, 0.f); v1 = fmaxf(v1, 0.f); }
        if (resA) {
            v0 += 0.5f * (resA[o0] + resB[o0]);
            v1 += 0.5f * (resA[o1] + resB[o1]);
        }
        out[o0] = v0;
        out[o1] = v1;
    }
}

// ---------------- host-side branch driver ----------------
static void run_branch(const float* mapV, const float* mapI,
                       const float* W1, const float* b1,
                       const float* W2, const float* b2,
                       const float* Wq, const float* Wk, const float* Wv, const float* Wo,
                       const float* intent,
                       float* score, int* idxp,
                       float* selV, float* selI,
                       float* q, float* k, float* v, float* o,
                       float* att, float* fs, float* outMap) {
    score_fused_kernel<<<256, 256>>>(mapV, mapI, intent, W1, b1, W2, b2, score);
    topk_kernel<<<4, 1024>>>(score, idxp);
    gather_kernel<<<16384, 256>>>(mapV, mapI, idxp, selV, selI);
    gemm_kernel<<<dim3(2, 64), 256>>>(selV, Wq, q, nullptr, nullptr, 4096, 128, 1024, 0);
    gemm_kernel<<<dim3(2, 64), 256>>>(selI, Wk, k, nullptr, nullptr, 4096, 128, 1024, 0);
    gemm_kernel<<<dim3(2, 64), 256>>>(selI, Wv, v, nullptr, nullptr, 4096, 128, 1024, 0);
    attn_scores_kernel<<<dim3(16, 16, 16), 256>>>(q, k, att);
    softmax_kernel<<<dim3(1024, 16), 256>>>(att);
    attn_apply_kernel<<<dim3(16, 16), 256>>>(att, v, o);
    gemm_kernel<<<dim3(16, 64), 256>>>(o, Wo, fs, nullptr, selV, 4096, 1024, 128, 0);
    avg_kernel<<<65536, 256>>>(mapV, mapI, outMap);
    scatter_kernel<<<16384, 256>>>(fs, idxp, outMap);
}

extern "C" void kernel_launch(void* const* d_in, const int* in_sizes, int n_in,
                              void* d_out, int out_size) {
    const float* vis  = (const float*)d_in[0];
    const float* ir   = (const float*)d_in[1];
    const float* bank = (const float*)d_in[2];
    const float* Wr   = (const float*)d_in[3];
    const float* br   = (const float*)d_in[4];
    const float* aW1  = (const float*)d_in[5];
    const float* ab1  = (const float*)d_in[6];
    const float* aW2  = (const float*)d_in[7];
    const float* ab2  = (const float*)d_in[8];
    const float* aWq  = (const float*)d_in[9];
    const float* aWk  = (const float*)d_in[10];
    const float* aWv  = (const float*)d_in[11];
    const float* aWo  = (const float*)d_in[12];
    const float* pW1  = (const float*)d_in[13];
    const float* pb1  = (const float*)d_in[14];
    const float* pW2  = (const float*)d_in[15];
    const float* pb2  = (const float*)d_in[16];
    const float* pWq  = (const float*)d_in[17];
    const float* pWk  = (const float*)d_in[18];
    const float* pWv  = (const float*)d_in[19];
    const float* pWo  = (const float*)d_in[20];
    const float* c1w  = (const float*)d_in[21];
    const float* c1b  = (const float*)d_in[22];
    const float* c2w  = (const float*)d_in[23];
    const float* c2b  = (const float*)d_in[24];
    float* out = (float*)d_out;

    float2* cA;
    float *ampV, *ampI, *phV, *phI, *faMap, *fpMap, *spatial, *r1;
    float *score, *selV, *selI, *q, *k, *v, *o, *att, *fs, *gm, *intent;
    int* idxp;
    cudaGetSymbolAddress((void**)&cA, g_cA);
    cudaGetSymbolAddress((void**)&ampV, g_ampV);
    cudaGetSymbolAddress((void**)&ampI, g_ampI);
    cudaGetSymbolAddress((void**)&phV, g_phV);
    cudaGetSymbolAddress((void**)&phI, g_phI);
    cudaGetSymbolAddress((void**)&faMap, g_faMap);
    cudaGetSymbolAddress((void**)&fpMap, g_fpMap);
    cudaGetSymbolAddress((void**)&spatial, g_spatial);
    cudaGetSymbolAddress((void**)&r1, g_r1);
    cudaGetSymbolAddress((void**)&score, g_scoreArr);
    cudaGetSymbolAddress((void**)&idxp, g_idxArr);
    cudaGetSymbolAddress((void**)&selV, g_selV);
    cudaGetSymbolAddress((void**)&selI, g_selI);
    cudaGetSymbolAddress((void**)&q, g_qb);
    cudaGetSymbolAddress((void**)&k, g_kb);
    cudaGetSymbolAddress((void**)&v, g_vb);
    cudaGetSymbolAddress((void**)&o, g_ob);
    cudaGetSymbolAddress((void**)&att, g_att);
    cudaGetSymbolAddress((void**)&fs, g_fs);
    cudaGetSymbolAddress((void**)&gm, g_gm);
    cudaGetSymbolAddress((void**)&intent, g_intentArr);

    twiddle_init_kernel<<<1, 256>>>();
    gap_kernel<<<512, 256>>>(vis, ir, gm);
    router_kernel<<<1, 64>>>(gm, Wr, br, bank, intent);

    const int FB = 4096;
    fft_pass2_kernel<<<FB, 256>>>(nullptr, vis, nullptr, nullptr, cA, nullptr, nullptr, nullptr, 0, +1, 1.f);
    fft_pass2_kernel<<<FB, 256>>>(cA, nullptr, nullptr, nullptr, nullptr, ampV, phV, nullptr, 1, +1, 1.f);
    fft_pass2_kernel<<<FB, 256>>>(nullptr, ir, nullptr, nullptr, cA, nullptr, nullptr, nullptr, 0, +1, 1.f);
    fft_pass2_kernel<<<FB, 256>>>(cA, nullptr, nullptr, nullptr, nullptr, ampI, phI, nullptr, 1, +1, 1.f);

    run_branch(ampV, ampI, aW1, ab1, aW2, ab2, aWq, aWk, aWv, aWo, intent,
               score, idxp, selV, selI, q, k, v, o, att, fs, faMap);
    run_branch(phV, phI, pW1, pb1, pW2, pb2, pWq, pWk, pWv, pWo, intent,
               score, idxp, selV, selI, q, k, v, o, att, fs, fpMap);

    fft_pass2_kernel<<<FB, 256>>>(nullptr, nullptr, faMap, fpMap, cA, nullptr, nullptr, nullptr, 0, -1, 1.f);
    fft_pass2_kernel<<<FB, 256>>>(cA, nullptr, nullptr, nullptr, nullptr, nullptr, nullptr, spatial, 1, -1, 1.0f / 65536.0f);

    conv3_kernel<<<dim3(16, 16, 4), 256>>>(spatial, c1w, c1b, r1, nullptr, nullptr, 1);
    conv3_kernel<<<dim3(16, 16, 4), 256>>>(r1, c2w, c2b, out, vis, ir, 0);

    (void)in_sizes; (void)n_in; (void)out_size;
}

// round 6
// speedup vs baseline: 1.2741x; 1.0965x over previous
#include <cuda_runtime.h>
#include <math.h>

// ---------------- problem constants ----------------
#define B_    4
#define C_    64
#define NPIX_ 16777216            // B*C*H*W
#define NT_   16384               // B * NPAT
#define TOK_  1024
#define SF_   2114
#define KSEL_ 1024
#define E_    128
#define SELSZ_ ((long)B_ * KSEL_ * TOK_)     // 4 Mi floats per branch
#define QSZ_   (B_ * KSEL_ * E_)             // 512 Ki floats per branch
#define ATTSZ_ ((long)B_ * 4 * KSEL_ * KSEL_) // 16 Mi floats per branch

typedef unsigned long long ull;

// ---------------- device scratch (2x for batched branches) ----------------
__device__ float2 g_cA[NPIX_];
__device__ float  g_ampV[NPIX_];
__device__ float  g_ampI[NPIX_];
__device__ float  g_phV [NPIX_];
__device__ float  g_phI [NPIX_];
__device__ float  g_faMap[NPIX_];
__device__ float  g_fpMap[NPIX_];
__device__ float  g_spatial[NPIX_];
__device__ float  g_r1[NPIX_];
__device__ float  g_scoreArr[2 * NT_];
__device__ int    g_idxArr[2 * B_ * KSEL_];
__device__ float  g_selV[2 * SELSZ_];
__device__ float  g_selI[2 * SELSZ_];
__device__ float  g_qb[2 * QSZ_];
__device__ float  g_kb[2 * QSZ_];
__device__ float  g_vb[2 * QSZ_];
__device__ float  g_ob[2 * QSZ_];
__device__ float  g_att[2 * ATTSZ_];
__device__ float  g_fs[2 * SELSZ_];
__device__ float  g_gm[B_ * 2 * C_];
__device__ float  g_intentArr[B_ * 64];
__device__ float  g_t256r[256];
__device__ float  g_t256i[256];

// ---------------- packed f32x2 helpers (sm_103a FFMA2) ----------------
__device__ __forceinline__ ull pk2(float lo, float hi) {
    ull r;
    asm("mov.b64 %0, {%1, %2};" : "=l"(r) : "f"(lo), "f"(hi));
    return r;
}
__device__ __forceinline__ void upk2(ull v, float& lo, float& hi) {
    asm("mov.b64 {%0, %1}, %2;" : "=f"(lo), "=f"(hi) : "l"(v));
}
#define FMA2_(d, a, b) asm("fma.rn.f32x2 %0, %1, %2, %0;" : "+l"(d) : "l"(a), "l"(b))

// ---------------- twiddles ----------------
__global__ void twiddle_init_kernel() {
    int k = threadIdx.x;
    double a = -2.0 * 3.14159265358979323846 * (double)k / 256.0;
    g_t256r[k] = (float)cos(a);
    g_t256i[k] = (float)sin(a);
}

// ---------------- 16-point register FFT ----------------
__device__ __forceinline__ void fft16_reg(float* xr, float* xi, float dsign) {
    #define SW16_(a,b) { float t=xr[a]; xr[a]=xr[b]; xr[b]=t; t=xi[a]; xi[a]=xi[b]; xi[b]=t; }
    SW16_(1,8) SW16_(2,4) SW16_(3,12) SW16_(5,10) SW16_(7,14) SW16_(11,13)
    #undef SW16_
    const float C16[8] = {1.f, 0.9238795325112867f, 0.7071067811865476f, 0.3826834323650898f,
                          0.f, -0.3826834323650898f, -0.7071067811865476f, -0.9238795325112867f};
    const float S16[8] = {0.f, 0.3826834323650898f, 0.7071067811865476f, 0.9238795325112867f,
                          1.f, 0.9238795325112867f, 0.7071067811865476f, 0.3826834323650898f};
    #pragma unroll
    for (int s = 1; s <= 4; s++) {
        const int half = 1 << (s - 1);
        #pragma unroll
        for (int j = 0; j < 8; j++) {
            const int grp = j >> (s - 1);
            const int pos = j & (half - 1);
            const int i = (grp << s) + pos;
            const int l = i + half;
            const int ti = pos << (4 - s);
            float wr = C16[ti];
            float wi = -dsign * S16[ti];
            float vr = xr[l] * wr - xi[l] * wi;
            float vi = xr[l] * wi + xi[l] * wr;
            float ur = xr[i], ui = xi[i];
            xr[i] = ur + vr; xi[i] = ui + vi;
            xr[l] = ur - vr; xi[l] = ui - vi;
        }
    }
}

// ---------------- 256-pt FFT pass ----------------
#define FFT_SM 4352
__global__ void fft_pass2_kernel(const float2* __restrict__ cin,
                                 const float* __restrict__ rin,
                                 const float* __restrict__ fa,
                                 const float* __restrict__ fp,
                                 float2* __restrict__ cout,
                                 float* __restrict__ amp,
                                 float* __restrict__ ph,
                                 float* __restrict__ rout,
                                 int colmode, int dir, float scale) {
    __shared__ float sre[FFT_SM];
    __shared__ float sim[FFT_SM];
    int tid = threadIdx.x;
    int tx = tid & 15, ty = tid >> 4;
    int u = colmode ? ty : tx;
    int s = colmode ? tx : ty;
    int line = blockIdx.x * 16 + s;
    int plane = line >> 8, l = line & 255;
    long base; int stride;
    if (colmode) { base = (long)plane * 65536 + l; stride = 256; }
    else         { base = (long)plane * 65536 + (long)l * 256; stride = 1; }
    float dsign = (dir > 0) ? 1.f : -1.f;

    float xr[16], xi[16];
    #pragma unroll
    for (int n2 = 0; n2 < 16; n2++) {
        long a = base + (long)(u + 16 * n2) * stride;
        if (rin)      { xr[n2] = rin[a]; xi[n2] = 0.f; }
        else if (fa)  { float am = fa[a]; float sn, cs; sincosf(fp[a], &sn, &cs);
                        xr[n2] = am * cs; xi[n2] = am * sn; }
        else          { float2 c = cin[a]; xr[n2] = c.x; xi[n2] = c.y; }
    }
    fft16_reg(xr, xi, dsign);
    #pragma unroll
    for (int k2 = 0; k2 < 16; k2++) {
        int m = u * k2;
        float wr = g_t256r[m];
        float wi = dsign * g_t256i[m];
        float a = xr[k2], b = xi[k2];
        xr[k2] = a * wr - b * wi;
        xi[k2] = a * wi + b * wr;
    }
    #pragma unroll
    for (int k2 = 0; k2 < 16; k2++) {
        int idx = colmode ? ((k2 * 16 + u) * 17 + s) : (s * 272 + k2 * 17 + u);
        sre[idx] = xr[k2]; sim[idx] = xi[k2];
    }
    __syncthreads();
    #pragma unroll
    for (int n1 = 0; n1 < 16; n1++) {
        int idx = colmode ? ((u * 16 + n1) * 17 + s) : (s * 272 + u * 17 + n1);
        xr[n1] = sre[idx]; xi[n1] = sim[idx];
    }
    fft16_reg(xr, xi, dsign);
    #pragma unroll
    for (int k1 = 0; k1 < 16; k1++) {
        long a = base + (long)(16 * k1 + u) * stride;
        float rr = xr[k1] * scale, ii = xi[k1] * scale;
        if (cout)      cout[a] = make_float2(rr, ii);
        else if (amp)  { amp[a] = sqrtf(rr * rr + ii * ii); ph[a] = atan2f(ii, rr); }
        else           rout[a] = rr;
    }
}

// ---------------- router ----------------
__global__ void gap_kernel(const float* __restrict__ vis, const float* __restrict__ ir,
                           float* __restrict__ gm) {
    __shared__ float red[256];
    int b = blockIdx.x >> 7;
    int ch = blockIdx.x & 127;
    const float* p = (ch < 64) ? (vis + (long)(b * 64 + ch) * 65536)
                               : (ir  + (long)(b * 64 + ch - 64) * 65536);
    float s = 0.f;
    for (int i = threadIdx.x; i < 65536; i += 256) s += p[i];
    red[threadIdx.x] = s;
    __syncthreads();
    for (int st = 128; st > 0; st >>= 1) {
        if (threadIdx.x < st) red[threadIdx.x] += red[threadIdx.x + st];
        __syncthreads();
    }
    if (threadIdx.x == 0) gm[blockIdx.x] = red[0] * (1.0f / 65536.0f);
}

__global__ void router_kernel(const float* __restrict__ gm, const float* __restrict__ Wr,
                              const float* __restrict__ br, const float* __restrict__ bank,
                              float* __restrict__ intent) {
    __shared__ float pf[4][64];
    __shared__ float lg[4][4];
    __shared__ float w[4][4];
    int t = threadIdx.x;
    for (int b = 0; b < 4; b++) {
        float s = br[t];
        for (int c = 0; c < 128; c++) s += gm[b * 128 + c] * Wr[c * 64 + t];
        pf[b][t] = s;
    }
    __syncthreads();
    if (t < 16) {
        int b = t >> 2, j = t & 3;
        float s = 0.f;
        for (int p = 0; p < 64; p++) s += pf[b][p] * bank[j * 64 + p];
        lg[b][j] = s;
    }
    __syncthreads();
    if (t < 4) {
        int b = t;
        float m = fmaxf(fmaxf(lg[b][0], lg[b][1]), fmaxf(lg[b][2], lg[b][3]));
        float e0 = expf(lg[b][0] - m), e1 = expf(lg[b][1] - m);
        float e2 = expf(lg[b][2] - m), e3 = expf(lg[b][3] - m);
        float s = e0 + e1 + e2 + e3;
        w[b][0] = e0 / s; w[b][1] = e1 / s; w[b][2] = e2 / s; w[b][3] = e3 / s;
    }
    __syncthreads();
    for (int b = 0; b < 4; b++) {
        float s = 0.f;
        for (int j = 0; j < 4; j++) s += w[b][j] * bank[j * 64 + t];
        intent[b * 64 + t] = s;
    }
}

// ---------------- fused score net, branch-batched, FMA2 inner ----------------
__global__ void __launch_bounds__(256) score_fused_kernel(
        const float* __restrict__ ampV, const float* __restrict__ ampI,
        const float* __restrict__ phV, const float* __restrict__ phI,
        const float* __restrict__ intent,
        const float* __restrict__ aW1, const float* __restrict__ ab1,
        const float* __restrict__ aW2, const float* __restrict__ ab2,
        const float* __restrict__ pW1, const float* __restrict__ pb1,
        const float* __restrict__ pW2, const float* __restrict__ pb2,
        float* __restrict__ score) {
    const int BM = 64, BK = 16;
    __shared__ float As[BK][68];
    __shared__ float Bs[BK][132];
    __shared__ float red[64 * 16];
    int brx = blockIdx.y;
    const float* mapV = brx ? phV : ampV;
    const float* mapI = brx ? phI : ampI;
    const float* W1 = brx ? pW1 : aW1;
    const float* b1 = brx ? pb1 : ab1;
    const float* W2 = brx ? pW2 : aW2;
    const float* b2 = brx ? pb2 : ab2;

    int tid = threadIdx.x;
    int row0 = blockIdx.x * BM;
    int ty = tid >> 4, tx = tid & 15;

    ull acc2[4][4];
    #pragma unroll
    for (int i = 0; i < 4; i++)
        #pragma unroll
        for (int jp = 0; jp < 4; jp++) acc2[i][jp] = 0ull;

    for (int k0 = 0; k0 < SF_; k0 += BK) {
        #pragma unroll
        for (int lq = 0; lq < 4; lq++) {
            int e = tid + lq * 256;
            int r = e >> 4, c = e & 15;
            int col = k0 + c;
            int tok = row0 + r;
            int b = tok >> 12, n = tok & 4095;
            float v = 0.f;
            if (col < 2048) {
                int t = col & 1023;
                int ch = t >> 4, py = (t >> 2) & 3, px = t & 3;
                int hy = n >> 6, wx = n & 63;
                long m = (((long)(b * 64 + ch) * 256) + hy * 4 + py) * 256 + wx * 4 + px;
                v = (col < 1024) ? mapV[m] : mapI[m];
            } else if (col < SF_) {
                if (col == 2048)      v = (float)(n >> 6) * (1.0f / 63.0f);
                else if (col == 2049) v = (float)(n & 63) * (1.0f / 63.0f);
                else                  v = intent[b * 64 + (col - 2050)];
            }
            As[c][r] = v;
        }
        #pragma unroll
        for (int lq = 0; lq < 8; lq++) {
            int e = tid + lq * 256;
            int r = e >> 7, c = e & 127;
            Bs[r][c] = (k0 + r < SF_) ? W1[(long)(k0 + r) * 128 + c] : 0.f;
        }
        __syncthreads();
        #pragma unroll
        for (int kk = 0; kk < BK; kk++) {
            float4 av = *(const float4*)&As[kk][ty * 4];
            ull a2[4] = {pk2(av.x, av.x), pk2(av.y, av.y), pk2(av.z, av.z), pk2(av.w, av.w)};
            const ull* bp = (const ull*)&Bs[kk][tx * 8];
            ull b2v[4] = {bp[0], bp[1], bp[2], bp[3]};
            #pragma unroll
            for (int i = 0; i < 4; i++)
                #pragma unroll
                for (int jp = 0; jp < 4; jp++)
                    FMA2_(acc2[i][jp], a2[i], b2v[jp]);
        }
        __syncthreads();
    }

    float w2[8], bs[8];
    #pragma unroll
    for (int j = 0; j < 8; j++) { w2[j] = W2[tx * 8 + j]; bs[j] = b1[tx * 8 + j]; }
    #pragma unroll
    for (int i = 0; i < 4; i++) {
        float p = 0.f;
        #pragma unroll
        for (int jp = 0; jp < 4; jp++) {
            float c0, c1;
            upk2(acc2[i][jp], c0, c1);
            float h0 = fmaxf(c0 + bs[2 * jp], 0.f);
            float h1 = fmaxf(c1 + bs[2 * jp + 1], 0.f);
            p += h0 * w2[2 * jp] + h1 * w2[2 * jp + 1];
        }
        red[(ty * 4 + i) * 16 + tx] = p;
    }
    __syncthreads();
    if (tid < 64) {
        float s = 0.f;
        #pragma unroll
        for (int q = 0; q < 16; q++) s += red[tid * 16 + q];
        score[brx * NT_ + row0 + tid] = s + b2[0];
    }
}

// ---------------- batched 64x128 FMA2 GEMM: C = A@W (+residual) ----------------
struct GB { const float* A; const float* W; float* C; const float* R; };
struct GB8 { GB g[8]; };

__global__ void __launch_bounds__(256) gemm_batched_kernel(GB8 gb, int M, int N, int K) {
    const int BK = 16;
    __shared__ float As[BK][68];
    __shared__ float Bs[BK][132];
    GB p = gb.g[blockIdx.z];
    int tid = threadIdx.x;
    int row0 = blockIdx.y * 64, col0 = blockIdx.x * 128;
    int ty = tid >> 4, tx = tid & 15;

    ull acc2[4][4];
    #pragma unroll
    for (int i = 0; i < 4; i++)
        #pragma unroll
        for (int jp = 0; jp < 4; jp++) acc2[i][jp] = 0ull;

    for (int k0 = 0; k0 < K; k0 += BK) {
        #pragma unroll
        for (int lq = 0; lq < 4; lq++) {
            int e = tid + lq * 256;
            int r = e >> 4, c = e & 15;
            As[c][r] = p.A[(long)(row0 + r) * K + (k0 + c)];
        }
        #pragma unroll
        for (int lq = 0; lq < 8; lq++) {
            int e = tid + lq * 256;
            int r = e >> 7, c = e & 127;
            Bs[r][c] = p.W[(long)(k0 + r) * N + (col0 + c)];
        }
        __syncthreads();
        #pragma unroll
        for (int kk = 0; kk < BK; kk++) {
            float4 av = *(const float4*)&As[kk][ty * 4];
            ull a2[4] = {pk2(av.x, av.x), pk2(av.y, av.y), pk2(av.z, av.z), pk2(av.w, av.w)};
            const ull* bp = (const ull*)&Bs[kk][tx * 8];
            ull b2v[4] = {bp[0], bp[1], bp[2], bp[3]};
            #pragma unroll
            for (int i = 0; i < 4; i++)
                #pragma unroll
                for (int jp = 0; jp < 4; jp++)
                    FMA2_(acc2[i][jp], a2[i], b2v[jp]);
        }
        __syncthreads();
    }
    #pragma unroll
    for (int i = 0; i < 4; i++) {
        long r = row0 + ty * 4 + i;
        #pragma unroll
        for (int jp = 0; jp < 4; jp++) {
            float v0, v1;
            upk2(acc2[i][jp], v0, v1);
            long c0 = col0 + tx * 8 + 2 * jp;
            if (p.R) {
                v0 += p.R[r * N + c0];
                v1 += p.R[r * N + c0 + 1];
            }
            p.C[r * N + c0]     = v0;
            p.C[r * N + c0 + 1] = v1;
        }
    }
}

// ---------------- top-k via bitonic sort (branch-batched) ----------------
__global__ void __launch_bounds__(1024) topk_kernel(const float* __restrict__ score,
                                                    int* __restrict__ idxo) {
    __shared__ float key[4096];
    __shared__ int val[4096];
    int b4 = blockIdx.x;                 // br*4 + batch
    int brx = b4 >> 2, b = b4 & 3;
    int t = threadIdx.x;
    const float* sp = score + brx * NT_ + b * 4096;
    for (int i = t; i < 4096; i += 1024) { key[i] = sp[i]; val[i] = i; }
    __syncthreads();
    for (int k = 2; k <= 4096; k <<= 1) {
        for (int j = k >> 1; j > 0; j >>= 1) {
            for (int i = t; i < 4096; i += 1024) {
                int ixj = i ^ j;
                if (ixj > i) {
                    bool desc = ((i & k) == 0);
                    float a = key[i], c = key[ixj];
                    bool sw = desc ? (a < c) : (a > c);
                    if (sw) {
                        key[i] = c; key[ixj] = a;
                        int tv = val[i]; val[i] = val[ixj]; val[ixj] = tv;
                    }
                }
            }
            __syncthreads();
        }
    }
    if (t < 1024) idxo[b4 * 1024 + t] = val[t];
}

// ---------------- gather / scatter (branch-batched) ----------------
__device__ __forceinline__ long patch_pixel(int b, int n, int t) {
    int hy = n >> 6, wx = n & 63;
    int c = t >> 4, py = (t >> 2) & 3, px = t & 3;
    return (((long)(b * 64 + c) * 256) + hy * 4 + py) * 256 + wx * 4 + px;
}

__global__ void gather_kernel(const float* __restrict__ ampV, const float* __restrict__ ampI,
                              const float* __restrict__ phV, const float* __restrict__ phI,
                              const int* __restrict__ idx,
                              float* __restrict__ selV, float* __restrict__ selI) {
    int brx = blockIdx.y;
    const float* mapV = brx ? phV : ampV;
    const float* mapI = brx ? phI : ampI;
    long gid = (long)blockIdx.x * 256 + threadIdx.x;
    int bi = (int)(gid >> 10);
    int t = (int)(gid & 1023);
    int b = bi >> 10;
    int n = idx[brx * 4096 + bi];
    long m = patch_pixel(b, n, t);
    long off = (long)brx * SELSZ_;
    selV[off + gid] = mapV[m];
    selI[off + gid] = mapI[m];
}

__global__ void scatter_kernel(const float* __restrict__ fs, const int* __restrict__ idx,
                               float* __restrict__ faMap, float* __restrict__ fpMap) {
    int brx = blockIdx.y;
    float* outMap = brx ? fpMap : faMap;
    long gid = (long)blockIdx.x * 256 + threadIdx.x;
    int bi = (int)(gid >> 10);
    int t = (int)(gid & 1023);
    int b = bi >> 10;
    int n = idx[brx * 4096 + bi];
    long m = patch_pixel(b, n, t);
    outMap[m] = fs[(long)brx * SELSZ_ + gid];
}

// ---------------- attention (branch-batched 3-kernel pipeline) ----------------
__global__ void attn_scores_kernel(const float* __restrict__ Q, const float* __restrict__ Kt,
                                   float* __restrict__ S) {
    __shared__ float Qs[64][33];
    __shared__ float Ks[64][33];
    int z = blockIdx.z;                 // 0..31 = br*16 + (b*4+h)
    int brx = z >> 4, zz = z & 15;
    int b = zz >> 2, h = zz & 3;
    const float* Qp = Q + (long)brx * QSZ_ + (long)b * 1024 * 128 + h * 32;
    const float* Kp = Kt + (long)brx * QSZ_ + (long)b * 1024 * 128 + h * 32;
    int i0 = blockIdx.y * 64, j0 = blockIdx.x * 64;
    int tid = threadIdx.x;
    #pragma unroll
    for (int l = 0; l < 8; l++) {
        int e = tid + l * 256;
        int r = e >> 5, c = e & 31;
        Qs[r][c] = Qp[(long)(i0 + r) * 128 + c];
        Ks[r][c] = Kp[(long)(j0 + r) * 128 + c];
    }
    __syncthreads();
    int ty = tid >> 4, tx = tid & 15;
    float acc[4][4];
    #pragma unroll
    for (int i = 0; i < 4; i++)
        #pragma unroll
        for (int j = 0; j < 4; j++) acc[i][j] = 0.f;
    #pragma unroll
    for (int d = 0; d < 32; d++) {
        float a[4], bb[4];
        #pragma unroll
        for (int i = 0; i < 4; i++) a[i] = Qs[ty * 4 + i][d];
        #pragma unroll
        for (int j = 0; j < 4; j++) bb[j] = Ks[tx * 4 + j][d];
        #pragma unroll
        for (int i = 0; i < 4; i++)
            #pragma unroll
            for (int j = 0; j < 4; j++) acc[i][j] += a[i] * bb[j];
    }
    const float scale = 0.17677669529663687f;
    #pragma unroll
    for (int i = 0; i < 4; i++)
        #pragma unroll
        for (int j = 0; j < 4; j++)
            S[((long)z * 1024 + i0 + ty * 4 + i) * 1024 + j0 + tx * 4 + j] = acc[i][j] * scale;
}

__global__ void softmax_kernel(float* __restrict__ S) {
    __shared__ float red[256];
    long base = ((long)blockIdx.y * 1024 + blockIdx.x) * 1024;
    int t = threadIdx.x;
    float v[4];
    float m = -3.4e38f;
    #pragma unroll
    for (int l = 0; l < 4; l++) { v[l] = S[base + t + l * 256]; m = fmaxf(m, v[l]); }
    red[t] = m;
    __syncthreads();
    for (int s = 128; s > 0; s >>= 1) {
        if (t < s) red[t] = fmaxf(red[t], red[t + s]);
        __syncthreads();
    }
    m = red[0];
    __syncthreads();
    float sum = 0.f;
    #pragma unroll
    for (int l = 0; l < 4; l++) { v[l] = __expf(v[l] - m); sum += v[l]; }
    red[t] = sum;
    __syncthreads();
    for (int s = 128; s > 0; s >>= 1) {
        if (t < s) red[t] += red[t + s];
        __syncthreads();
    }
    float inv = 1.0f / red[0];
    #pragma unroll
    for (int l = 0; l < 4; l++) S[base + t + l * 256] = v[l] * inv;
}

__global__ void attn_apply_kernel(const float* __restrict__ S, const float* __restrict__ V,
                                  float* __restrict__ O) {
    __shared__ float Ps[64][65];
    __shared__ float Vs[64][33];
    int z = blockIdx.y;                 // 0..31
    int brx = z >> 4, zz = z & 15;
    int b = zz >> 2, h = zz & 3;
    int i0 = blockIdx.x * 64;
    int tid = threadIdx.x;
    int ty = tid >> 5, tx = tid & 31;
    const float* Vp = V + (long)brx * QSZ_;
    float* Op = O + (long)brx * QSZ_;
    float acc[8];
    #pragma unroll
    for (int q = 0; q < 8; q++) acc[q] = 0.f;
    for (int j0 = 0; j0 < 1024; j0 += 64) {
        #pragma unroll
        for (int l = 0; l < 16; l++) {
            int e = tid + l * 256;
            int r = e >> 6, c = e & 63;
            Ps[r][c] = S[((long)z * 1024 + i0 + r) * 1024 + j0 + c];
        }
        #pragma unroll
        for (int l = 0; l < 8; l++) {
            int e = tid + l * 256;
            int r = e >> 5, c = e & 31;
            Vs[r][c] = Vp[(long)(b * 1024 + j0 + r) * 128 + h * 32 + c];
        }
        __syncthreads();
        #pragma unroll
        for (int kk = 0; kk < 64; kk++) {
            float vv = Vs[kk][tx];
            #pragma unroll
            for (int q = 0; q < 8; q++) acc[q] += Ps[ty * 8 + q][kk] * vv;
        }
        __syncthreads();
    }
    #pragma unroll
    for (int q = 0; q < 8; q++)
        Op[(long)(b * 1024 + i0 + ty * 8 + q) * 128 + h * 32 + tx] = acc[q];
}

// ---------------- elementwise avg (branch-batched) ----------------
__global__ void avg_kernel(const float* __restrict__ ampV, const float* __restrict__ ampI,
                           float* __restrict__ faMap,
                           const float* __restrict__ phV, const float* __restrict__ phI,
                           float* __restrict__ fpMap) {
    int brx = blockIdx.y;
    long i = (long)blockIdx.x * 256 + threadIdx.x;
    if (brx == 0) faMap[i] = 0.5f * (ampV[i] + ampI[i]);
    else          fpMap[i] = 0.5f * (phV[i] + phI[i]);
}

// ---------------- 3x3 SAME conv: 16x16 tile, 64 co/block, channel-pair FMA2 ----------------
__global__ void __launch_bounds__(256) conv3_kernel(
        const float* __restrict__ in, const float* __restrict__ wgt,
        const float* __restrict__ bias, float* __restrict__ out,
        const float* __restrict__ resA, const float* __restrict__ resB,
        int relu) {
    __shared__ float sIn[18][18];
    __shared__ float2 sW2[32][9];
    int bz = blockIdx.z;
    int x0 = blockIdx.x * 16, y0 = blockIdx.y * 16;
    int tx = threadIdx.x & 15, ty = threadIdx.x >> 4;
    int tid = threadIdx.x;
    int x = x0 + tx, y = y0 + ty;

    ull acc[32];
    #pragma unroll
    for (int p = 0; p < 32; p++) acc[p] = 0ull;

    for (int ci = 0; ci < 64; ci++) {
        const float* ip = in + (long)(bz * 64 + ci) * 65536;
        for (int e = tid; e < 324; e += 256) {
            int ry = e / 18, rx = e % 18;
            int gy = y0 + ry - 1, gx = x0 + rx - 1;
            sIn[ry][rx] = (gy >= 0 && gy < 256 && gx >= 0 && gx < 256) ? ip[gy * 256 + gx] : 0.f;
        }
        for (int e = tid; e < 288; e += 256) {
            int p = e / 9, k = e % 9;
            sW2[p][k] = make_float2(wgt[((long)(2 * p) * 64 + ci) * 9 + k],
                                    wgt[((long)(2 * p + 1) * 64 + ci) * 9 + k]);
        }
        __syncthreads();
        ull vp[9];
        #pragma unroll
        for (int ky = 0; ky < 3; ky++)
            #pragma unroll
            for (int kx = 0; kx < 3; kx++) {
                float v = sIn[ty + ky][tx + kx];
                vp[ky * 3 + kx] = pk2(v, v);
            }
        #pragma unroll
        for (int p = 0; p < 32; p++) {
            #pragma unroll
            for (int k = 0; k < 9; k++) {
                ull w2 = *(const ull*)&sW2[p][k];
                FMA2_(acc[p], vp[k], w2);
            }
        }
        __syncthreads();
    }
    #pragma unroll
    for (int p = 0; p < 32; p++) {
        float v0, v1;
        upk2(acc[p], v0, v1);
        int co0 = 2 * p, co1 = 2 * p + 1;
        long o0 = ((long)(bz * 64 + co0) * 256 + y) * 256 + x;
        long o1 = ((long)(bz * 64 + co1) * 256 + y) * 256 + x;
        v0 += bias[co0];
        v1 += bias[co1];
        if (relu) { v0 = fmaxf(v0, 0.f); v1 = fmaxf(v1, 0.f); }
        if (resA) {
            v0 += 0.5f * (resA[o0] + resB[o0]);
            v1 += 0.5f * (resA[o1] + resB[o1]);
        }
        out[o0] = v0;
        out[o1] = v1;
    }
}

extern "C" void kernel_launch(void* const* d_in, const int* in_sizes, int n_in,
                              void* d_out, int out_size) {
    const float* vis  = (const float*)d_in[0];
    const float* ir   = (const float*)d_in[1];
    const float* bank = (const float*)d_in[2];
    const float* Wr   = (const float*)d_in[3];
    const float* br   = (const float*)d_in[4];
    const float* aW1  = (const float*)d_in[5];
    const float* ab1  = (const float*)d_in[6];
    const float* aW2  = (const float*)d_in[7];
    const float* ab2  = (const float*)d_in[8];
    const float* aWq  = (const float*)d_in[9];
    const float* aWk  = (const float*)d_in[10];
    const float* aWv  = (const float*)d_in[11];
    const float* aWo  = (const float*)d_in[12];
    const float* pW1  = (const float*)d_in[13];
    const float* pb1  = (const float*)d_in[14];
    const float* pW2  = (const float*)d_in[15];
    const float* pb2  = (const float*)d_in[16];
    const float* pWq  = (const float*)d_in[17];
    const float* pWk  = (const float*)d_in[18];
    const float* pWv  = (const float*)d_in[19];
    const float* pWo  = (const float*)d_in[20];
    const float* c1w  = (const float*)d_in[21];
    const float* c1b  = (const float*)d_in[22];
    const float* c2w  = (const float*)d_in[23];
    const float* c2b  = (const float*)d_in[24];
    float* out = (float*)d_out;

    float2* cA;
    float *ampV, *ampI, *phV, *phI, *faMap, *fpMap, *spatial, *r1;
    float *score, *selV, *selI, *q, *k, *v, *o, *att, *fs, *gm, *intent;
    int* idxp;
    cudaGetSymbolAddress((void**)&cA, g_cA);
    cudaGetSymbolAddress((void**)&ampV, g_ampV);
    cudaGetSymbolAddress((void**)&ampI, g_ampI);
    cudaGetSymbolAddress((void**)&phV, g_phV);
    cudaGetSymbolAddress((void**)&phI, g_phI);
    cudaGetSymbolAddress((void**)&faMap, g_faMap);
    cudaGetSymbolAddress((void**)&fpMap, g_fpMap);
    cudaGetSymbolAddress((void**)&spatial, g_spatial);
    cudaGetSymbolAddress((void**)&r1, g_r1);
    cudaGetSymbolAddress((void**)&score, g_scoreArr);
    cudaGetSymbolAddress((void**)&idxp, g_idxArr);
    cudaGetSymbolAddress((void**)&selV, g_selV);
    cudaGetSymbolAddress((void**)&selI, g_selI);
    cudaGetSymbolAddress((void**)&q, g_qb);
    cudaGetSymbolAddress((void**)&k, g_kb);
    cudaGetSymbolAddress((void**)&v, g_vb);
    cudaGetSymbolAddress((void**)&o, g_ob);
    cudaGetSymbolAddress((void**)&att, g_att);
    cudaGetSymbolAddress((void**)&fs, g_fs);
    cudaGetSymbolAddress((void**)&gm, g_gm);
    cudaGetSymbolAddress((void**)&intent, g_intentArr);

    twiddle_init_kernel<<<1, 256>>>();
    gap_kernel<<<512, 256>>>(vis, ir, gm);
    router_kernel<<<1, 64>>>(gm, Wr, br, bank, intent);

    const int FB = 4096;
    fft_pass2_kernel<<<FB, 256>>>(nullptr, vis, nullptr, nullptr, cA, nullptr, nullptr, nullptr, 0, +1, 1.f);
    fft_pass2_kernel<<<FB, 256>>>(cA, nullptr, nullptr, nullptr, nullptr, ampV, phV, nullptr, 1, +1, 1.f);
    fft_pass2_kernel<<<FB, 256>>>(nullptr, ir, nullptr, nullptr, cA, nullptr, nullptr, nullptr, 0, +1, 1.f);
    fft_pass2_kernel<<<FB, 256>>>(cA, nullptr, nullptr, nullptr, nullptr, ampI, phI, nullptr, 1, +1, 1.f);

    // ----- batched branch pipeline -----
    score_fused_kernel<<<dim3(256, 2), 256>>>(ampV, ampI, phV, phI, intent,
                                              aW1, ab1, aW2, ab2, pW1, pb1, pW2, pb2, score);
    topk_kernel<<<8, 1024>>>(score, idxp);
    gather_kernel<<<dim3(16384, 2), 256>>>(ampV, ampI, phV, phI, idxp, selV, selI);

    GB8 qkv;
    qkv.g[0] = { selV,          aWq, q,          nullptr };
    qkv.g[1] = { selI,          aWk, k,          nullptr };
    qkv.g[2] = { selI,          aWv, v,          nullptr };
    qkv.g[3] = { selV + SELSZ_, pWq, q + QSZ_,   nullptr };
    qkv.g[4] = { selI + SELSZ_, pWk, k + QSZ_,   nullptr };
    qkv.g[5] = { selI + SELSZ_, pWv, v + QSZ_,   nullptr };
    qkv.g[6] = { nullptr, nullptr, nullptr, nullptr };
    qkv.g[7] = { nullptr, nullptr, nullptr, nullptr };
    gemm_batched_kernel<<<dim3(1, 64, 6), 256>>>(qkv, 4096, 128, 1024);

    attn_scores_kernel<<<dim3(16, 16, 32), 256>>>(q, k, att);
    softmax_kernel<<<dim3(1024, 32), 256>>>(att);
    attn_apply_kernel<<<dim3(16, 32), 256>>>(att, v, o);

    GB8 wo;
    wo.g[0] = { o,        aWo, fs,          selV };
    wo.g[1] = { o + QSZ_, pWo, fs + SELSZ_, selV + SELSZ_ };
    for (int z = 2; z < 8; z++) wo.g[z] = { nullptr, nullptr, nullptr, nullptr };
    gemm_batched_kernel<<<dim3(8, 64, 2), 256>>>(wo, 4096, 1024, 128);

    avg_kernel<<<dim3(65536, 2), 256>>>(ampV, ampI, faMap, phV, phI, fpMap);
    scatter_kernel<<<dim3(16384, 2), 256>>>(fs, idxp, faMap, fpMap);

    fft_pass2_kernel<<<FB, 256>>>(nullptr, nullptr, faMap, fpMap, cA, nullptr, nullptr, nullptr, 0, -1, 1.f);
    fft_pass2_kernel<<<FB, 256>>>(cA, nullptr, nullptr, nullptr, nullptr, nullptr, nullptr, spatial, 1, -1, 1.0f / 65536.0f);

    conv3_kernel<<<dim3(16, 16, 4), 256>>>(spatial, c1w, c1b, r1, nullptr, nullptr, 1);
    conv3_kernel<<<dim3(16, 16, 4), 256>>>(r1, c2w, c2b, out, vis, ir, 0);

    (void)in_sizes; (void)n_in; (void)out_size;
}